// round 8
// baseline (speedup 1.0000x reference)
#include <cuda_runtime.h>
#include <math.h>

constexpr int B = 32;

typedef unsigned long long u64;
#define FFMA2(acc, v, w) \
    asm("fma.rn.f32x2 %0, %1, %2, %3;" : "=l"(acc) : "l"(v), "l"(w), "l"(acc))
__device__ __forceinline__ u64 pack2(float a, float b) {
    u64 r; asm("mov.b64 %0, {%1, %2};" : "=l"(r) : "f"(a), "f"(b)); return r;
}
__device__ __forceinline__ float2 unpack2(u64 v) {
    float2 f; asm("mov.b64 {%0, %1}, %2;" : "=f"(f.x), "=f"(f.y) : "l"(v)); return f;
}

// ---- tf32 tensor-core helpers ----
__device__ __forceinline__ unsigned f2tf(float f) {
    unsigned u; asm("cvt.rna.tf32.f32 %0, %1;" : "=r"(u) : "f"(f)); return u;
}
#define MMA_TF32(c0, c1, c2, c3, a0, a1, a2, a3, b0, b1) \
    asm("mma.sync.aligned.m16n8k8.row.col.f32.tf32.tf32.f32 " \
        "{%0,%1,%2,%3}, {%4,%5,%6,%7}, {%8,%9}, {%0,%1,%2,%3};" \
        : "+f"(c0), "+f"(c1), "+f"(c2), "+f"(c3) \
        : "r"(a0), "r"(a1), "r"(a2), "r"(a3), "r"(b0), "r"(b1))

// ---- padded planes (strides multiple of 4 floats; halos stay zero forever) ----
constexpr int XP_P = 258 * 260;
constexpr int H1_P = 130 * 132;
constexpr int Z_P  = 66 * 68;

__device__ float g_xp [B * 3 * XP_P];
__device__ float g_h1p[B * 32 * H1_P];
__device__ float g_h2 [B * 64 * 4096];
__device__ float g_z  [B * 8 * 4096];
__device__ float g_zqp[B * 8 * Z_P];
__device__ int   g_idx[B * 4096];
__device__ float g_part[4096];
__device__ float g_d1p[B * 64 * Z_P];
__device__ float g_t1p[B * 64 * H1_P];
__device__ float g_t2p[B * 32 * XP_P];

constexpr int XR_ELEMS = B * 3 * 65536;
constexpr int LOSS_OFF = XR_ELEMS;
constexpr int IDX_OFF  = XR_ELEMS + 1;

// 18-float strip (for k4s2 convs)
struct S18 { float4 a, b, c, d; float2 e; };
__device__ __forceinline__ S18 ld18(const float* r) {
    S18 s;
    s.a = *(const float4*)(r);      s.b = *(const float4*)(r + 4);
    s.c = *(const float4*)(r + 8);  s.d = *(const float4*)(r + 12);
    s.e = *(const float2*)(r + 16);
    return s;
}
__device__ __forceinline__ void unp18(const S18& s, float* f) {
    *(float4*)&f[0] = s.a; *(float4*)&f[4] = s.b;
    *(float4*)&f[8] = s.c; *(float4*)&f[12] = s.d;
    *(float2*)&f[16] = s.e;
}
// 10-float strip
struct S10 { float4 a, b; float2 c; };
__device__ __forceinline__ S10 ld10(const float* r) {
    S10 s;
    s.a = *(const float4*)(r); s.b = *(const float4*)(r + 4);
    s.c = *(const float2*)(r + 8);
    return s;
}
__device__ __forceinline__ void unp10(const S10& s, float* f) {
    *(float4*)&f[0] = s.a; *(float4*)&f[4] = s.b; *(float2*)&f[8] = s.c;
}

// =====================================================================
// pad x. grid: 24576 x 256
// =====================================================================
__global__ __launch_bounds__(256) void k_pad(const float* __restrict__ x) {
    int i = blockIdx.x * 256 + threadIdx.x;
    int c = i >> 16, hw = i & 65535;
    int y = hw >> 8, xx = hw & 255;
    g_xp[(size_t)c * XP_P + (y + 1) * 260 + xx + 1] = x[i];
}

// =====================================================================
// conv1: 3->32, k4 s2 p1, 256->128, ReLU. 8co x 8px. grid 1024 x 256
// =====================================================================
__global__ __launch_bounds__(256) void k_conv1(const float* __restrict__ w,
                                               const float* __restrict__ bias) {
    __shared__ float ws[48 * 32];
    for (int i = threadIdx.x; i < 1536; i += 256) {
        int t = i >> 5, co = i & 31;
        int ci = t >> 4, k = t & 15;
        ws[i] = w[(co * 3 + ci) * 16 + k];
    }
    __syncthreads();
    int n = blockIdx.x >> 5, oyg = blockIdx.x & 31;
    int cog = threadIdx.x >> 6, oyl = (threadIdx.x >> 4) & 3, v0 = threadIdx.x & 15;
    int oy = oyg * 4 + oyl, ox0 = v0 * 8;
    u64 acc[4][8];
#pragma unroll
    for (int cp = 0; cp < 4; cp++) {
        u64 bv = pack2(bias[cog * 8 + 2 * cp], bias[cog * 8 + 2 * cp + 1]);
#pragma unroll
        for (int j = 0; j < 8; j++) acc[cp][j] = bv;
    }
    const float* base = g_xp + (size_t)n * 3 * XP_P + 2 * oy * 260 + 2 * ox0;
    S18 cur = ld18(base);
#pragma unroll 1
    for (int idx = 0; idx < 12; idx++) {
        int nx = idx < 11 ? idx + 1 : 11;
        S18 nxt = ld18(base + (nx >> 2) * XP_P + (nx & 3) * 260);
        float f[18]; unp18(cur, f);
        u64 fb[18];
#pragma unroll
        for (int i = 0; i < 18; i++) fb[i] = pack2(f[i], f[i]);
        int ci = idx >> 2, ky = idx & 3;
#pragma unroll
        for (int kx = 0; kx < 4; kx++) {
            const u64* wr = (const u64*)&ws[(ci * 16 + ky * 4 + kx) * 32 + cog * 8];
            u64 w0 = wr[0], w1 = wr[1], w2 = wr[2], w3 = wr[3];
#pragma unroll
            for (int j = 0; j < 8; j++) {
                u64 vv = fb[2 * j + kx];
                FFMA2(acc[0][j], vv, w0); FFMA2(acc[1][j], vv, w1);
                FFMA2(acc[2][j], vv, w2); FFMA2(acc[3][j], vv, w3);
            }
        }
        cur = nxt;
    }
    float* o = g_h1p + (size_t)n * 32 * H1_P + (oy + 1) * 132 + ox0 + 1;
#pragma unroll
    for (int cp = 0; cp < 4; cp++)
#pragma unroll
        for (int j = 0; j < 8; j++) {
            float2 fo = unpack2(acc[cp][j]);
            o[(cog * 8 + 2 * cp)     * H1_P + j] = fmaxf(fo.x, 0.f);
            o[(cog * 8 + 2 * cp + 1) * H1_P + j] = fmaxf(fo.y, 0.f);
        }
}

// =====================================================================
// conv2: 32->64, k4 s2 p1, 128->64, ReLU. 8co x 8px. grid 512 x 256
// =====================================================================
__global__ __launch_bounds__(256) void k_conv2(const float* __restrict__ w,
                                               const float* __restrict__ bias) {
    __shared__ float ws[8 * 16 * 64];
    int n = blockIdx.x >> 4, oyg = blockIdx.x & 15;
    int cog = threadIdx.x >> 5, oyl = (threadIdx.x >> 3) & 3, v0 = threadIdx.x & 7;
    int oy = oyg * 4 + oyl, ox0 = v0 * 8;
    u64 acc[4][8];
#pragma unroll
    for (int cp = 0; cp < 4; cp++) {
        u64 bv = pack2(bias[cog * 8 + 2 * cp], bias[cog * 8 + 2 * cp + 1]);
#pragma unroll
        for (int j = 0; j < 8; j++) acc[cp][j] = bv;
    }
    const float* xin = g_h1p + (size_t)n * 32 * H1_P + 2 * oy * 132 + 2 * ox0;
#pragma unroll 1
    for (int cc = 0; cc < 4; cc++) {
        __syncthreads();
        for (int i = threadIdx.x; i < 8192; i += 256) {
            int t = i >> 6, co = i & 63;
            int cl = t >> 4, k = t & 15;
            ws[i] = w[(co * 32 + cc * 8 + cl) * 16 + k];
        }
        __syncthreads();
        const float* base = xin + cc * 8 * H1_P;
        S18 cur = ld18(base);
#pragma unroll 1
        for (int idx = 0; idx < 32; idx++) {
            int nx = idx < 31 ? idx + 1 : 31;
            S18 nxt = ld18(base + (nx >> 2) * H1_P + (nx & 3) * 132);
            float f[18]; unp18(cur, f);
            u64 fb[18];
#pragma unroll
            for (int i = 0; i < 18; i++) fb[i] = pack2(f[i], f[i]);
            int cl = idx >> 2, ky = idx & 3;
#pragma unroll
            for (int kx = 0; kx < 4; kx++) {
                const u64* wr = (const u64*)&ws[(cl * 16 + ky * 4 + kx) * 64 + cog * 8];
                u64 w0 = wr[0], w1 = wr[1], w2 = wr[2], w3 = wr[3];
#pragma unroll
                for (int j = 0; j < 8; j++) {
                    u64 vv = fb[2 * j + kx];
                    FFMA2(acc[0][j], vv, w0); FFMA2(acc[1][j], vv, w1);
                    FFMA2(acc[2][j], vv, w2); FFMA2(acc[3][j], vv, w3);
                }
            }
            cur = nxt;
        }
    }
    float* o = g_h2 + (size_t)n * 64 * 4096 + oy * 64 + ox0;
#pragma unroll
    for (int cp = 0; cp < 4; cp++)
#pragma unroll
        for (int j = 0; j < 8; j++) {
            float2 fo = unpack2(acc[cp][j]);
            o[(cog * 8 + 2 * cp)     * 4096 + j] = fmaxf(fo.x, 0.f);
            o[(cog * 8 + 2 * cp + 1) * 4096 + j] = fmaxf(fo.y, 0.f);
        }
}

// =====================================================================
// conv3: 1x1, 64->8. grid: 512 x 256
// =====================================================================
__global__ __launch_bounds__(256) void k_conv3(const float* __restrict__ w,
                                               const float* __restrict__ bias) {
    __shared__ float ws[64 * 8];
    for (int i = threadIdx.x; i < 512; i += 256) {
        int ci = i >> 3, co = i & 7;
        ws[i] = w[co * 64 + ci];
    }
    __syncthreads();
    int n = blockIdx.x >> 4;
    int p = ((blockIdx.x & 15) << 8) + threadIdx.x;
    u64 acc[4];
#pragma unroll
    for (int c = 0; c < 4; c++) acc[c] = pack2(bias[2 * c], bias[2 * c + 1]);
    const float* xin = g_h2 + (size_t)n * 64 * 4096;
#pragma unroll 8
    for (int ci = 0; ci < 64; ci++) {
        float v = xin[ci * 4096 + p];
        u64 vv = pack2(v, v);
        const u64* wr = (const u64*)&ws[ci * 8];
#pragma unroll
        for (int c = 0; c < 4; c++) FFMA2(acc[c], vv, wr[c]);
    }
    float* o = g_z + (size_t)n * 8 * 4096;
#pragma unroll
    for (int c = 0; c < 4; c++) {
        float2 f = unpack2(acc[c]);
        o[(2 * c)     * 4096 + p] = f.x;
        o[(2 * c + 1) * 4096 + p] = f.y;
    }
}

// =====================================================================
// VQ argmin. grid: 1024 x 128
// =====================================================================
__global__ __launch_bounds__(128) void k_vq(const float* __restrict__ cb) {
    __shared__ float cs[512 * 8];
    __shared__ float csq[512];
    for (int i = threadIdx.x; i < 4096; i += 128) cs[i] = cb[i];
    __syncthreads();
    for (int k = threadIdx.x; k < 512; k += 128) {
        float s = 0.f;
#pragma unroll
        for (int d = 0; d < 8; d++) { float c = cs[k * 8 + d]; s += c * c; }
        csq[k] = s;
    }
    __syncthreads();
    int p = blockIdx.x * 128 + threadIdx.x;
    int n = p >> 12, hw = p & 4095;
    const float* zp = g_z + (size_t)n * 8 * 4096 + hw;
    float zv[8]; float zsq = 0.f;
#pragma unroll
    for (int d = 0; d < 8; d++) { zv[d] = zp[d * 4096]; zsq += zv[d] * zv[d]; }
    float best = 3.4e38f; int bi = 0;
    for (int k = 0; k < 512; k++) {
        float dot = 0.f;
#pragma unroll
        for (int d = 0; d < 8; d++) dot = fmaf(zv[d], cs[k * 8 + d], dot);
        float dist = zsq + csq[k] - 2.f * dot;
        if (dist < best) { best = dist; bi = k; }
    }
    g_idx[p] = bi;
}

// =====================================================================
// z_q gather + loss partials. grid: 4096 x 256
// =====================================================================
__global__ __launch_bounds__(256) void k_zq(const float* __restrict__ cb) {
    int i = blockIdx.x * 256 + threadIdx.x;
    float q = cb[g_idx[i >> 3] * 8 + (i & 7)];
    int n = i >> 15, c = (i >> 12) & 7, hw = i & 4095;
    int y = hw >> 6, xx = hw & 63;
    g_zqp[(size_t)(n * 8 + c) * Z_P + (y + 1) * 68 + xx + 1] = q;
    float diff = g_z[i] - q;
    float v = diff * diff;
    __shared__ float red[256];
    red[threadIdx.x] = v; __syncthreads();
    for (int s = 128; s > 0; s >>= 1) {
        if (threadIdx.x < s) red[threadIdx.x] += red[threadIdx.x + s];
        __syncthreads();
    }
    if (threadIdx.x == 0) g_part[blockIdx.x] = red[0];
}

__global__ __launch_bounds__(256) void k_loss(float* __restrict__ out) {
    __shared__ float red[256];
    float s = 0.f;
    for (int i = threadIdx.x; i < 4096; i += 256) s += g_part[i];
    red[threadIdx.x] = s; __syncthreads();
    for (int st = 128; st > 0; st >>= 1) {
        if (threadIdx.x < st) red[threadIdx.x] += red[threadIdx.x + st];
        __syncthreads();
    }
    if (threadIdx.x == 0) out[LOSS_OFF] = red[0] * (1.25f / 1048576.f);
}

__global__ __launch_bounds__(256) void k_idxout(float* __restrict__ out) {
    int p = blockIdx.x * 256 + threadIdx.x;
    if (p < B * 4096) out[IDX_OFF + p] = (float)g_idx[p];
}

// =====================================================================
// dconv1: 3x3 p1, 8->64, ReLU. 8co x 8px. grid 512 x 256
// =====================================================================
__global__ __launch_bounds__(256) void k_dconv1(const float* __restrict__ w,
                                                const float* __restrict__ bias) {
    __shared__ float ws[8 * 9 * 64];
    for (int i = threadIdx.x; i < 4608; i += 256) {
        int t = i >> 6, co = i & 63;
        int ci = t / 9, k = t % 9;
        ws[i] = w[(co * 8 + ci) * 9 + k];
    }
    __syncthreads();
    int n = blockIdx.x >> 4, oyg = blockIdx.x & 15;
    int cog = threadIdx.x >> 5, oyl = (threadIdx.x >> 3) & 3, v0 = threadIdx.x & 7;
    int oy = oyg * 4 + oyl, ox0 = v0 * 8;
    u64 acc[4][8];
#pragma unroll
    for (int cp = 0; cp < 4; cp++) {
        u64 bv = pack2(bias[cog * 8 + 2 * cp], bias[cog * 8 + 2 * cp + 1]);
#pragma unroll
        for (int j = 0; j < 8; j++) acc[cp][j] = bv;
    }
    const float* base = g_zqp + (size_t)n * 8 * Z_P + oy * 68 + ox0;
    S10 cur = ld10(base);
#pragma unroll 1
    for (int idx = 0; idx < 24; idx++) {
        int nx = idx < 23 ? idx + 1 : 23;
        S10 nxt = ld10(base + (nx / 3) * Z_P + (nx % 3) * 68);
        float f[10]; unp10(cur, f);
        u64 fb[10];
#pragma unroll
        for (int i = 0; i < 10; i++) fb[i] = pack2(f[i], f[i]);
        int ci = idx / 3, ky = idx % 3;
#pragma unroll
        for (int kx = 0; kx < 3; kx++) {
            const u64* wr = (const u64*)&ws[(ci * 9 + ky * 3 + kx) * 64 + cog * 8];
            u64 w0 = wr[0], w1 = wr[1], w2 = wr[2], w3 = wr[3];
#pragma unroll
            for (int j = 0; j < 8; j++) {
                u64 vv = fb[j + kx];
                FFMA2(acc[0][j], vv, w0); FFMA2(acc[1][j], vv, w1);
                FFMA2(acc[2][j], vv, w2); FFMA2(acc[3][j], vv, w3);
            }
        }
        cur = nxt;
    }
    float* o = g_d1p + (size_t)n * 64 * Z_P + (oy + 1) * 68 + ox0 + 1;
#pragma unroll
    for (int cp = 0; cp < 4; cp++)
#pragma unroll
        for (int j = 0; j < 8; j++) {
            float2 fo = unpack2(acc[cp][j]);
            o[(cog * 8 + 2 * cp)     * Z_P + j] = fmaxf(fo.x, 0.f);
            o[(cog * 8 + 2 * cp + 1) * Z_P + j] = fmaxf(fo.y, 0.f);
        }
}

// =====================================================================
// dect1 (TENSOR): 64->64, k4 s2 p1, 64->128, ReLU. tf32 mma per parity.
// GEMM per parity plane: M = 64x64 px, K = 64ci*4tap = 256, N = 64 co.
// Block 256thr = 8 warps: 4u x 2vhalf; co-half from grid. Warp: 32px x 32co.
// grid (1024, 4): x = n*32 + uq*2 + cohalf; y = parity
// =====================================================================
template<int PY, int PX>
__device__ __forceinline__ void dect1_mma(const float* __restrict__ wgt,
                                          const float* __restrict__ bias) {
    __shared__ unsigned sB[32 * 260];  // [co_local][k], k stride 260
    int n = blockIdx.x >> 5, r5 = blockIdx.x & 31;
    int uq = r5 >> 1, cob = (r5 & 1) * 32;
    int w = threadIdx.x >> 5, lane = threadIdx.x & 31;
    int lr = lane >> 2, lc = lane & 3;
    int u = 4 * uq + (w >> 1), v0m = (w & 1) * 32;

    // stage B[co][k] as tf32 (k = ci*4 + dy*2 + dx)
    for (int i = threadIdx.x; i < 8192; i += 256) {
        int col = i & 31, k = i >> 5;
        int ci = k >> 2, dy = (k >> 1) & 1, dx = k & 1;
        sB[col * 260 + k] = f2tf(
            wgt[((cob + col) * 64 + ci) * 16 + (PY + 2 * dy) * 4 + PX + 2 * dx]);
    }
    __syncthreads();

    float acc[2][4][4];
#pragma unroll
    for (int mt = 0; mt < 2; mt++)
#pragma unroll
        for (int nt = 0; nt < 4; nt++) {
            float b0 = bias[cob + nt * 8 + 2 * lc];
            float b1 = bias[cob + nt * 8 + 2 * lc + 1];
            acc[mt][nt][0] = b0; acc[mt][nt][1] = b1;
            acc[mt][nt][2] = b0; acc[mt][nt][3] = b1;
        }

    int dy = lc >> 1, dx = lc & 1;
    const float* A0 = g_d1p + (size_t)n * 64 * Z_P + (u + PY + dy) * 68
                    + (v0m + PX + dx) + lr;
#pragma unroll 1
    for (int ks = 0; ks < 32; ks++) {
        const float* p0 = A0 + (size_t)(2 * ks) * Z_P;
        unsigned af[2][4];
#pragma unroll
        for (int mt = 0; mt < 2; mt++) {
            const float* pa = p0 + mt * 16;
            af[mt][0] = f2tf(pa[0]);
            af[mt][1] = f2tf(pa[8]);
            af[mt][2] = f2tf(pa[Z_P]);
            af[mt][3] = f2tf(pa[Z_P + 8]);
        }
#pragma unroll
        for (int nt = 0; nt < 4; nt++) {
            unsigned b0 = sB[(nt * 8 + lr) * 260 + 8 * ks + lc];
            unsigned b1 = sB[(nt * 8 + lr) * 260 + 8 * ks + lc + 4];
            MMA_TF32(acc[0][nt][0], acc[0][nt][1], acc[0][nt][2], acc[0][nt][3],
                     af[0][0], af[0][1], af[0][2], af[0][3], b0, b1);
            MMA_TF32(acc[1][nt][0], acc[1][nt][1], acc[1][nt][2], acc[1][nt][3],
                     af[1][0], af[1][1], af[1][2], af[1][3], b0, b1);
        }
    }
    float* ob = g_t1p + (size_t)n * 64 * H1_P + (2 * u + PY + 1) * 132
              + PX + 1 + 2 * v0m;
#pragma unroll
    for (int mt = 0; mt < 2; mt++)
#pragma unroll
        for (int nt = 0; nt < 4; nt++) {
            int co0 = cob + nt * 8 + 2 * lc;
            float* o = ob + 2 * (mt * 16 + lr);
            o[(size_t)co0 * H1_P]            = fmaxf(acc[mt][nt][0], 0.f);
            o[(size_t)(co0 + 1) * H1_P]      = fmaxf(acc[mt][nt][1], 0.f);
            o[(size_t)co0 * H1_P + 16]       = fmaxf(acc[mt][nt][2], 0.f);
            o[(size_t)(co0 + 1) * H1_P + 16] = fmaxf(acc[mt][nt][3], 0.f);
        }
}

__global__ __launch_bounds__(256) void k_dect1(const float* __restrict__ w,
                                               const float* __restrict__ bias) {
    switch (blockIdx.y) {
        case 0: dect1_mma<0, 0>(w, bias); break;
        case 1: dect1_mma<0, 1>(w, bias); break;
        case 2: dect1_mma<1, 0>(w, bias); break;
        default: dect1_mma<1, 1>(w, bias); break;
    }
}

// =====================================================================
// dect2 (TENSOR): 64->32, k4 s2 p1, 128->256, ReLU. tf32 mma per parity.
// GEMM per parity: M = 128x128 px, K = 256, N = 32 co.
// Block 256thr = 8 warps: 2u x 4vchunk. Warp: 32px x 32co.
// grid (2048, 4): x = n*64 + up; y = parity
// =====================================================================
template<int PY, int PX>
__device__ __forceinline__ void dect2_mma(const float* __restrict__ wgt,
                                          const float* __restrict__ bias) {
    __shared__ unsigned sB[32 * 260];
    int n = blockIdx.x >> 6, up = blockIdx.x & 63;
    int w = threadIdx.x >> 5, lane = threadIdx.x & 31;
    int lr = lane >> 2, lc = lane & 3;
    int u = 2 * up + (w >> 2), v0m = (w & 3) * 32;

    for (int i = threadIdx.x; i < 8192; i += 256) {
        int col = i & 31, k = i >> 5;
        int ci = k >> 2, dy = (k >> 1) & 1, dx = k & 1;
        sB[col * 260 + k] = f2tf(
            wgt[(col * 64 + ci) * 16 + (PY + 2 * dy) * 4 + PX + 2 * dx]);
    }
    __syncthreads();

    float acc[2][4][4];
#pragma unroll
    for (int mt = 0; mt < 2; mt++)
#pragma unroll
        for (int nt = 0; nt < 4; nt++) {
            float b0 = bias[nt * 8 + 2 * lc];
            float b1 = bias[nt * 8 + 2 * lc + 1];
            acc[mt][nt][0] = b0; acc[mt][nt][1] = b1;
            acc[mt][nt][2] = b0; acc[mt][nt][3] = b1;
        }

    int dy = lc >> 1, dx = lc & 1;
    const float* A0 = g_t1p + (size_t)n * 64 * H1_P + (u + PY + dy) * 132
                    + (v0m + PX + dx) + lr;
#pragma unroll 1
    for (int ks = 0; ks < 32; ks++) {
        const float* p0 = A0 + (size_t)(2 * ks) * H1_P;
        unsigned af[2][4];
#pragma unroll
        for (int mt = 0; mt < 2; mt++) {
            const float* pa = p0 + mt * 16;
            af[mt][0] = f2tf(pa[0]);
            af[mt][1] = f2tf(pa[8]);
            af[mt][2] = f2tf(pa[H1_P]);
            af[mt][3] = f2tf(pa[H1_P + 8]);
        }
#pragma unroll
        for (int nt = 0; nt < 4; nt++) {
            unsigned b0 = sB[(nt * 8 + lr) * 260 + 8 * ks + lc];
            unsigned b1 = sB[(nt * 8 + lr) * 260 + 8 * ks + lc + 4];
            MMA_TF32(acc[0][nt][0], acc[0][nt][1], acc[0][nt][2], acc[0][nt][3],
                     af[0][0], af[0][1], af[0][2], af[0][3], b0, b1);
            MMA_TF32(acc[1][nt][0], acc[1][nt][1], acc[1][nt][2], acc[1][nt][3],
                     af[1][0], af[1][1], af[1][2], af[1][3], b0, b1);
        }
    }
    float* ob = g_t2p + (size_t)n * 32 * XP_P + (2 * u + PY + 1) * 260
              + PX + 1 + 2 * v0m;
#pragma unroll
    for (int mt = 0; mt < 2; mt++)
#pragma unroll
        for (int nt = 0; nt < 4; nt++) {
            int co0 = nt * 8 + 2 * lc;
            float* o = ob + 2 * (mt * 16 + lr);
            o[(size_t)co0 * XP_P]            = fmaxf(acc[mt][nt][0], 0.f);
            o[(size_t)(co0 + 1) * XP_P]      = fmaxf(acc[mt][nt][1], 0.f);
            o[(size_t)co0 * XP_P + 16]       = fmaxf(acc[mt][nt][2], 0.f);
            o[(size_t)(co0 + 1) * XP_P + 16] = fmaxf(acc[mt][nt][3], 0.f);
        }
}

__global__ __launch_bounds__(256) void k_dect2(const float* __restrict__ w,
                                               const float* __restrict__ bias) {
    switch (blockIdx.y) {
        case 0: dect2_mma<0, 0>(w, bias); break;
        case 1: dect2_mma<0, 1>(w, bias); break;
        case 2: dect2_mma<1, 0>(w, bias); break;
        default: dect2_mma<1, 1>(w, bias); break;
    }
}

// =====================================================================
// dconv2: 3x3 p1, 32->3, sigmoid. 4 px/thread, pipelined over ci. grid 2048 x 256
// =====================================================================
__global__ __launch_bounds__(256) void k_dconv2(const float* __restrict__ w,
                                                const float* __restrict__ bias,
                                                float* __restrict__ out) {
    __shared__ u64 ws2[32 * 9 * 3];
    for (int i = threadIdx.x; i < 32 * 9; i += 256) {
        int ci = i / 9, k = i % 9;
#pragma unroll
        for (int co = 0; co < 3; co++) {
            float wv = w[(co * 32 + ci) * 9 + k];
            ws2[i * 3 + co] = pack2(wv, wv);
        }
    }
    __syncthreads();
    int n = blockIdx.x >> 6;
    int p = ((blockIdx.x & 63) << 8) + threadIdx.x;
    int X = p & 63, oy = p >> 6;
    int ox0 = 4 * X;

    u64 acc[3][2];
#pragma unroll
    for (int co = 0; co < 3; co++) {
        float bv = bias[co];
        acc[co][0] = pack2(bv, bv);
        acc[co][1] = acc[co][0];
    }
    const float* xin = g_t2p + (size_t)n * 32 * XP_P + oy * 260 + ox0;
    float4 cA[3]; float2 cB[3];
#pragma unroll
    for (int ry = 0; ry < 3; ry++) {
        cA[ry] = *(const float4*)(xin + ry * 260);
        cB[ry] = *(const float2*)(xin + ry * 260 + 4);
    }
#pragma unroll 1
    for (int ci = 0; ci < 32; ci++) {
        const float* pn = xin + (ci < 31 ? ci + 1 : ci) * XP_P;
        float4 nA[3]; float2 nB[3];
#pragma unroll
        for (int ry = 0; ry < 3; ry++) {
            nA[ry] = *(const float4*)(pn + ry * 260);
            nB[ry] = *(const float2*)(pn + ry * 260 + 4);
        }
        float in[3][6];
#pragma unroll
        for (int ry = 0; ry < 3; ry++) {
            *(float4*)&in[ry][0] = cA[ry];
            *(float2*)&in[ry][4] = cB[ry];
        }
        u64 pr[3][5];
#pragma unroll
        for (int ry = 0; ry < 3; ry++)
#pragma unroll
            for (int i = 0; i < 5; i++)
                pr[ry][i] = pack2(in[ry][i], in[ry][i + 1]);
#pragma unroll
        for (int ky = 0; ky < 3; ky++)
#pragma unroll
            for (int kx = 0; kx < 3; kx++) {
                const u64* wr = &ws2[(ci * 9 + ky * 3 + kx) * 3];
#pragma unroll
                for (int co = 0; co < 3; co++) {
                    FFMA2(acc[co][0], pr[ky][kx],     wr[co]);
                    FFMA2(acc[co][1], pr[ky][kx + 2], wr[co]);
                }
            }
#pragma unroll
        for (int ry = 0; ry < 3; ry++) { cA[ry] = nA[ry]; cB[ry] = nB[ry]; }
    }
    float* o = out + (size_t)n * 3 * 65536 + oy * 256 + ox0;
#pragma unroll
    for (int co = 0; co < 3; co++) {
        float2 f0 = unpack2(acc[co][0]);
        float2 f1 = unpack2(acc[co][1]);
        o[co * 65536 + 0] = 1.f / (1.f + expf(-f0.x));
        o[co * 65536 + 1] = 1.f / (1.f + expf(-f0.y));
        o[co * 65536 + 2] = 1.f / (1.f + expf(-f1.x));
        o[co * 65536 + 3] = 1.f / (1.f + expf(-f1.y));
    }
}

// =====================================================================
extern "C" void kernel_launch(void* const* d_in, const int* in_sizes, int n_in,
                              void* d_out, int out_size) {
    const float* x       = (const float*)d_in[0];
    const float* enc_w1  = (const float*)d_in[1];
    const float* enc_b1  = (const float*)d_in[2];
    const float* enc_w2  = (const float*)d_in[3];
    const float* enc_b2  = (const float*)d_in[4];
    const float* enc_w3  = (const float*)d_in[5];
    const float* enc_b3  = (const float*)d_in[6];
    const float* codebook= (const float*)d_in[7];
    const float* dec_w1  = (const float*)d_in[8];
    const float* dec_b1  = (const float*)d_in[9];
    const float* dect_w1 = (const float*)d_in[10];
    const float* dect_b1 = (const float*)d_in[11];
    const float* dect_w2 = (const float*)d_in[12];
    const float* dect_b2 = (const float*)d_in[13];
    const float* dec_w2  = (const float*)d_in[14];
    const float* dec_b2  = (const float*)d_in[15];
    float* out = (float*)d_out;

    k_pad   <<<24576, 256>>>(x);
    k_conv1 <<<1024,  256>>>(enc_w1, enc_b1);
    k_conv2 <<<512,   256>>>(enc_w2, enc_b2);
    k_conv3 <<<512,   256>>>(enc_w3, enc_b3);
    k_vq    <<<1024,  128>>>(codebook);
    k_zq    <<<4096,  256>>>(codebook);
    k_loss  <<<1,     256>>>(out);
    k_idxout<<<512,   256>>>(out);
    k_dconv1<<<512,   256>>>(dec_w1, dec_b1);
    k_dect1 <<<dim3(1024, 4), 256>>>(dect_w1, dect_b1);
    k_dect2 <<<dim3(2048, 4), 256>>>(dect_w2, dect_b2);
    k_dconv2<<<2048,  256>>>(dec_w2, dec_b2, out);
}

// round 9
// speedup vs baseline: 1.4159x; 1.4159x over previous
#include <cuda_runtime.h>
#include <math.h>

constexpr int B = 32;

typedef unsigned long long u64;
#define FFMA2(acc, v, w) \
    asm("fma.rn.f32x2 %0, %1, %2, %3;" : "=l"(acc) : "l"(v), "l"(w), "l"(acc))
__device__ __forceinline__ u64 pack2(float a, float b) {
    u64 r; asm("mov.b64 %0, {%1, %2};" : "=l"(r) : "f"(a), "f"(b)); return r;
}
__device__ __forceinline__ float2 unpack2(u64 v) {
    float2 f; asm("mov.b64 {%0, %1}, %2;" : "=f"(f.x), "=f"(f.y) : "l"(v)); return f;
}

#define MMA_TF32(c0, c1, c2, c3, a0, a1, a2, a3, b0, b1) \
    asm("mma.sync.aligned.m16n8k8.row.col.f32.tf32.tf32.f32 " \
        "{%0,%1,%2,%3}, {%4,%5,%6,%7}, {%8,%9}, {%0,%1,%2,%3};" \
        : "+f"(c0), "+f"(c1), "+f"(c2), "+f"(c3) \
        : "r"(a0), "r"(a1), "r"(a2), "r"(a3), "r"(b0), "r"(b1))

// ---- padded planes ----
constexpr int XP_P = 258 * 260;
constexpr int H1_P = 130 * 132;
constexpr int Z_P  = 66 * 68;

__device__ float g_xp [B * 3 * XP_P];
__device__ float g_h1p[B * 32 * H1_P];
__device__ float g_h2 [B * 64 * 4096];
__device__ float g_z  [B * 8 * 4096];
__device__ float g_zqp[B * 8 * Z_P];
__device__ int   g_idx[B * 4096];
__device__ float g_part[4096];
__device__ float g_d1p[B * 64 * Z_P];
__device__ float g_t1p[B * 64 * H1_P];
__device__ float g_t2p[B * 32 * XP_P];

constexpr int XR_ELEMS = B * 3 * 65536;
constexpr int LOSS_OFF = XR_ELEMS;
constexpr int IDX_OFF  = XR_ELEMS + 1;

struct S18 { float4 a, b, c, d; float2 e; };
__device__ __forceinline__ S18 ld18(const float* r) {
    S18 s;
    s.a = *(const float4*)(r);      s.b = *(const float4*)(r + 4);
    s.c = *(const float4*)(r + 8);  s.d = *(const float4*)(r + 12);
    s.e = *(const float2*)(r + 16);
    return s;
}
__device__ __forceinline__ void unp18(const S18& s, float* f) {
    *(float4*)&f[0] = s.a; *(float4*)&f[4] = s.b;
    *(float4*)&f[8] = s.c; *(float4*)&f[12] = s.d;
    *(float2*)&f[16] = s.e;
}
struct S10 { float4 a, b; float2 c; };
__device__ __forceinline__ S10 ld10(const float* r) {
    S10 s;
    s.a = *(const float4*)(r); s.b = *(const float4*)(r + 4);
    s.c = *(const float2*)(r + 8);
    return s;
}
__device__ __forceinline__ void unp10(const S10& s, float* f) {
    *(float4*)&f[0] = s.a; *(float4*)&f[4] = s.b; *(float2*)&f[8] = s.c;
}

// =====================================================================
__global__ __launch_bounds__(256) void k_pad(const float* __restrict__ x) {
    int i = blockIdx.x * 256 + threadIdx.x;
    int c = i >> 16, hw = i & 65535;
    int y = hw >> 8, xx = hw & 255;
    g_xp[(size_t)c * XP_P + (y + 1) * 260 + xx + 1] = x[i];
}

// =====================================================================
// conv1: 3->32, k4 s2 p1. 8co x 8px. grid 1024 x 256
// =====================================================================
__global__ __launch_bounds__(256) void k_conv1(const float* __restrict__ w,
                                               const float* __restrict__ bias) {
    __shared__ float ws[48 * 32];
    for (int i = threadIdx.x; i < 1536; i += 256) {
        int t = i >> 5, co = i & 31;
        int ci = t >> 4, k = t & 15;
        ws[i] = w[(co * 3 + ci) * 16 + k];
    }
    __syncthreads();
    int n = blockIdx.x >> 5, oyg = blockIdx.x & 31;
    int cog = threadIdx.x >> 6, oyl = (threadIdx.x >> 4) & 3, v0 = threadIdx.x & 15;
    int oy = oyg * 4 + oyl, ox0 = v0 * 8;
    u64 acc[4][8];
#pragma unroll
    for (int cp = 0; cp < 4; cp++) {
        u64 bv = pack2(bias[cog * 8 + 2 * cp], bias[cog * 8 + 2 * cp + 1]);
#pragma unroll
        for (int j = 0; j < 8; j++) acc[cp][j] = bv;
    }
    const float* base = g_xp + (size_t)n * 3 * XP_P + 2 * oy * 260 + 2 * ox0;
    S18 cur = ld18(base);
#pragma unroll 1
    for (int idx = 0; idx < 12; idx++) {
        int nx = idx < 11 ? idx + 1 : 11;
        S18 nxt = ld18(base + (nx >> 2) * XP_P + (nx & 3) * 260);
        float f[18]; unp18(cur, f);
        u64 fb[18];
#pragma unroll
        for (int i = 0; i < 18; i++) fb[i] = pack2(f[i], f[i]);
        int ci = idx >> 2, ky = idx & 3;
#pragma unroll
        for (int kx = 0; kx < 4; kx++) {
            const u64* wr = (const u64*)&ws[(ci * 16 + ky * 4 + kx) * 32 + cog * 8];
            u64 w0 = wr[0], w1 = wr[1], w2 = wr[2], w3 = wr[3];
#pragma unroll
            for (int j = 0; j < 8; j++) {
                u64 vv = fb[2 * j + kx];
                FFMA2(acc[0][j], vv, w0); FFMA2(acc[1][j], vv, w1);
                FFMA2(acc[2][j], vv, w2); FFMA2(acc[3][j], vv, w3);
            }
        }
        cur = nxt;
    }
    float* o = g_h1p + (size_t)n * 32 * H1_P + (oy + 1) * 132 + ox0 + 1;
#pragma unroll
    for (int cp = 0; cp < 4; cp++)
#pragma unroll
        for (int j = 0; j < 8; j++) {
            float2 fo = unpack2(acc[cp][j]);
            o[(cog * 8 + 2 * cp)     * H1_P + j] = fmaxf(fo.x, 0.f);
            o[(cog * 8 + 2 * cp + 1) * H1_P + j] = fmaxf(fo.y, 0.f);
        }
}

// =====================================================================
// conv2: 32->64, k4 s2 p1. 8co x 8px. grid 512 x 256
// =====================================================================
__global__ __launch_bounds__(256) void k_conv2(const float* __restrict__ w,
                                               const float* __restrict__ bias) {
    __shared__ float ws[8 * 16 * 64];
    int n = blockIdx.x >> 4, oyg = blockIdx.x & 15;
    int cog = threadIdx.x >> 5, oyl = (threadIdx.x >> 3) & 3, v0 = threadIdx.x & 7;
    int oy = oyg * 4 + oyl, ox0 = v0 * 8;
    u64 acc[4][8];
#pragma unroll
    for (int cp = 0; cp < 4; cp++) {
        u64 bv = pack2(bias[cog * 8 + 2 * cp], bias[cog * 8 + 2 * cp + 1]);
#pragma unroll
        for (int j = 0; j < 8; j++) acc[cp][j] = bv;
    }
    const float* xin = g_h1p + (size_t)n * 32 * H1_P + 2 * oy * 132 + 2 * ox0;
#pragma unroll 1
    for (int cc = 0; cc < 4; cc++) {
        __syncthreads();
        for (int i = threadIdx.x; i < 8192; i += 256) {
            int t = i >> 6, co = i & 63;
            int cl = t >> 4, k = t & 15;
            ws[i] = w[(co * 32 + cc * 8 + cl) * 16 + k];
        }
        __syncthreads();
        const float* base = xin + cc * 8 * H1_P;
        S18 cur = ld18(base);
#pragma unroll 1
        for (int idx = 0; idx < 32; idx++) {
            int nx = idx < 31 ? idx + 1 : 31;
            S18 nxt = ld18(base + (nx >> 2) * H1_P + (nx & 3) * 132);
            float f[18]; unp18(cur, f);
            u64 fb[18];
#pragma unroll
            for (int i = 0; i < 18; i++) fb[i] = pack2(f[i], f[i]);
            int cl = idx >> 2, ky = idx & 3;
#pragma unroll
            for (int kx = 0; kx < 4; kx++) {
                const u64* wr = (const u64*)&ws[(cl * 16 + ky * 4 + kx) * 64 + cog * 8];
                u64 w0 = wr[0], w1 = wr[1], w2 = wr[2], w3 = wr[3];
#pragma unroll
                for (int j = 0; j < 8; j++) {
                    u64 vv = fb[2 * j + kx];
                    FFMA2(acc[0][j], vv, w0); FFMA2(acc[1][j], vv, w1);
                    FFMA2(acc[2][j], vv, w2); FFMA2(acc[3][j], vv, w3);
                }
            }
            cur = nxt;
        }
    }
    float* o = g_h2 + (size_t)n * 64 * 4096 + oy * 64 + ox0;
#pragma unroll
    for (int cp = 0; cp < 4; cp++)
#pragma unroll
        for (int j = 0; j < 8; j++) {
            float2 fo = unpack2(acc[cp][j]);
            o[(cog * 8 + 2 * cp)     * 4096 + j] = fmaxf(fo.x, 0.f);
            o[(cog * 8 + 2 * cp + 1) * 4096 + j] = fmaxf(fo.y, 0.f);
        }
}

// =====================================================================
// conv3: 1x1, 64->8. grid: 512 x 256
// =====================================================================
__global__ __launch_bounds__(256) void k_conv3(const float* __restrict__ w,
                                               const float* __restrict__ bias) {
    __shared__ float ws[64 * 8];
    for (int i = threadIdx.x; i < 512; i += 256) {
        int ci = i >> 3, co = i & 7;
        ws[i] = w[co * 64 + ci];
    }
    __syncthreads();
    int n = blockIdx.x >> 4;
    int p = ((blockIdx.x & 15) << 8) + threadIdx.x;
    u64 acc[4];
#pragma unroll
    for (int c = 0; c < 4; c++) acc[c] = pack2(bias[2 * c], bias[2 * c + 1]);
    const float* xin = g_h2 + (size_t)n * 64 * 4096;
#pragma unroll 8
    for (int ci = 0; ci < 64; ci++) {
        float v = xin[ci * 4096 + p];
        u64 vv = pack2(v, v);
        const u64* wr = (const u64*)&ws[ci * 8];
#pragma unroll
        for (int c = 0; c < 4; c++) FFMA2(acc[c], vv, wr[c]);
    }
    float* o = g_z + (size_t)n * 8 * 4096;
#pragma unroll
    for (int c = 0; c < 4; c++) {
        float2 f = unpack2(acc[c]);
        o[(2 * c)     * 4096 + p] = f.x;
        o[(2 * c + 1) * 4096 + p] = f.y;
    }
}

// =====================================================================
// VQ argmin. grid: 1024 x 128
// =====================================================================
__global__ __launch_bounds__(128) void k_vq(const float* __restrict__ cb) {
    __shared__ float cs[512 * 8];
    __shared__ float csq[512];
    for (int i = threadIdx.x; i < 4096; i += 128) cs[i] = cb[i];
    __syncthreads();
    for (int k = threadIdx.x; k < 512; k += 128) {
        float s = 0.f;
#pragma unroll
        for (int d = 0; d < 8; d++) { float c = cs[k * 8 + d]; s += c * c; }
        csq[k] = s;
    }
    __syncthreads();
    int p = blockIdx.x * 128 + threadIdx.x;
    int n = p >> 12, hw = p & 4095;
    const float* zp = g_z + (size_t)n * 8 * 4096 + hw;
    float zv[8]; float zsq = 0.f;
#pragma unroll
    for (int d = 0; d < 8; d++) { zv[d] = zp[d * 4096]; zsq += zv[d] * zv[d]; }
    float best = 3.4e38f; int bi = 0;
    for (int k = 0; k < 512; k++) {
        float dot = 0.f;
#pragma unroll
        for (int d = 0; d < 8; d++) dot = fmaf(zv[d], cs[k * 8 + d], dot);
        float dist = zsq + csq[k] - 2.f * dot;
        if (dist < best) { best = dist; bi = k; }
    }
    g_idx[p] = bi;
}

// =====================================================================
// z_q gather + loss partials. grid: 4096 x 256
// =====================================================================
__global__ __launch_bounds__(256) void k_zq(const float* __restrict__ cb) {
    int i = blockIdx.x * 256 + threadIdx.x;
    float q = cb[g_idx[i >> 3] * 8 + (i & 7)];
    int n = i >> 15, c = (i >> 12) & 7, hw = i & 4095;
    int y = hw >> 6, xx = hw & 63;
    g_zqp[(size_t)(n * 8 + c) * Z_P + (y + 1) * 68 + xx + 1] = q;
    float diff = g_z[i] - q;
    float v = diff * diff;
    __shared__ float red[256];
    red[threadIdx.x] = v; __syncthreads();
    for (int s = 128; s > 0; s >>= 1) {
        if (threadIdx.x < s) red[threadIdx.x] += red[threadIdx.x + s];
        __syncthreads();
    }
    if (threadIdx.x == 0) g_part[blockIdx.x] = red[0];
}

__global__ __launch_bounds__(256) void k_loss(float* __restrict__ out) {
    __shared__ float red[256];
    float s = 0.f;
    for (int i = threadIdx.x; i < 4096; i += 256) s += g_part[i];
    red[threadIdx.x] = s; __syncthreads();
    for (int st = 128; st > 0; st >>= 1) {
        if (threadIdx.x < st) red[threadIdx.x] += red[threadIdx.x + st];
        __syncthreads();
    }
    if (threadIdx.x == 0) out[LOSS_OFF] = red[0] * (1.25f / 1048576.f);
}

__global__ __launch_bounds__(256) void k_idxout(float* __restrict__ out) {
    int p = blockIdx.x * 256 + threadIdx.x;
    if (p < B * 4096) out[IDX_OFF + p] = (float)g_idx[p];
}

// =====================================================================
// dconv1: 3x3 p1, 8->64. 8co x 8px. grid 512 x 256
// =====================================================================
__global__ __launch_bounds__(256) void k_dconv1(const float* __restrict__ w,
                                                const float* __restrict__ bias) {
    __shared__ float ws[8 * 9 * 64];
    for (int i = threadIdx.x; i < 4608; i += 256) {
        int t = i >> 6, co = i & 63;
        int ci = t / 9, k = t % 9;
        ws[i] = w[(co * 8 + ci) * 9 + k];
    }
    __syncthreads();
    int n = blockIdx.x >> 4, oyg = blockIdx.x & 15;
    int cog = threadIdx.x >> 5, oyl = (threadIdx.x >> 3) & 3, v0 = threadIdx.x & 7;
    int oy = oyg * 4 + oyl, ox0 = v0 * 8;
    u64 acc[4][8];
#pragma unroll
    for (int cp = 0; cp < 4; cp++) {
        u64 bv = pack2(bias[cog * 8 + 2 * cp], bias[cog * 8 + 2 * cp + 1]);
#pragma unroll
        for (int j = 0; j < 8; j++) acc[cp][j] = bv;
    }
    const float* base = g_zqp + (size_t)n * 8 * Z_P + oy * 68 + ox0;
    S10 cur = ld10(base);
#pragma unroll 1
    for (int idx = 0; idx < 24; idx++) {
        int nx = idx < 23 ? idx + 1 : 23;
        S10 nxt = ld10(base + (nx / 3) * Z_P + (nx % 3) * 68);
        float f[10]; unp10(cur, f);
        u64 fb[10];
#pragma unroll
        for (int i = 0; i < 10; i++) fb[i] = pack2(f[i], f[i]);
        int ci = idx / 3, ky = idx % 3;
#pragma unroll
        for (int kx = 0; kx < 3; kx++) {
            const u64* wr = (const u64*)&ws[(ci * 9 + ky * 3 + kx) * 64 + cog * 8];
            u64 w0 = wr[0], w1 = wr[1], w2 = wr[2], w3 = wr[3];
#pragma unroll
            for (int j = 0; j < 8; j++) {
                u64 vv = fb[j + kx];
                FFMA2(acc[0][j], vv, w0); FFMA2(acc[1][j], vv, w1);
                FFMA2(acc[2][j], vv, w2); FFMA2(acc[3][j], vv, w3);
            }
        }
        cur = nxt;
    }
    float* o = g_d1p + (size_t)n * 64 * Z_P + (oy + 1) * 68 + ox0 + 1;
#pragma unroll
    for (int cp = 0; cp < 4; cp++)
#pragma unroll
        for (int j = 0; j < 8; j++) {
            float2 fo = unpack2(acc[cp][j]);
            o[(cog * 8 + 2 * cp)     * Z_P + j] = fmaxf(fo.x, 0.f);
            o[(cog * 8 + 2 * cp + 1) * Z_P + j] = fmaxf(fo.y, 0.f);
        }
}

// =====================================================================
// dect1 (tf32 mma v2): per parity M=64x64px, K=256, N=64.
// Warp: M=64 (full v row) x N=32. CTA: 8 u-rows x 32 co.
// grid (512, 4): x = n*16 + ub*2 + cohalf
// =====================================================================
template<int PY, int PX>
__device__ __forceinline__ void dect1_mma(const float* __restrict__ wgt,
                                          const float* __restrict__ bias) {
    __shared__ unsigned sB[32 * 260];
    int n = blockIdx.x >> 4, r = blockIdx.x & 15;
    int ub = r >> 1, cob = (r & 1) * 32;
    int w = threadIdx.x >> 5, lane = threadIdx.x & 31;
    int lr = lane >> 2, lc = lane & 3;
    int u = 8 * ub + w;

    for (int i = threadIdx.x; i < 8192; i += 256) {
        int col = i & 31, k = i >> 5;
        int ci = k >> 2, dy = (k >> 1) & 1, dx = k & 1;
        sB[col * 260 + k] = __float_as_uint(
            wgt[((cob + col) * 64 + ci) * 16 + (PY + 2 * dy) * 4 + PX + 2 * dx]);
    }
    __syncthreads();

    float acc[4][4][4];
#pragma unroll
    for (int mt = 0; mt < 4; mt++)
#pragma unroll
        for (int nt = 0; nt < 4; nt++) {
            float b0 = bias[cob + nt * 8 + 2 * lc];
            float b1 = bias[cob + nt * 8 + 2 * lc + 1];
            acc[mt][nt][0] = b0; acc[mt][nt][1] = b1;
            acc[mt][nt][2] = b0; acc[mt][nt][3] = b1;
        }

    int dy = lc >> 1, dx = lc & 1;
    const float* A0 = g_d1p + (size_t)n * 64 * Z_P + (u + PY + dy) * 68
                    + (PX + dx) + lr;
#pragma unroll 1
    for (int ks = 0; ks < 32; ks++) {
        const float* p0 = A0 + (size_t)(2 * ks) * Z_P;
        unsigned af[4][4];
#pragma unroll
        for (int mt = 0; mt < 4; mt++) {
            const float* pa = p0 + mt * 16;
            af[mt][0] = __float_as_uint(pa[0]);
            af[mt][1] = __float_as_uint(pa[8]);
            af[mt][2] = __float_as_uint(pa[Z_P]);
            af[mt][3] = __float_as_uint(pa[Z_P + 8]);
        }
#pragma unroll
        for (int nt = 0; nt < 4; nt++) {
            unsigned b0 = sB[(nt * 8 + lr) * 260 + 8 * ks + lc];
            unsigned b1 = sB[(nt * 8 + lr) * 260 + 8 * ks + lc + 4];
#pragma unroll
            for (int mt = 0; mt < 4; mt++)
                MMA_TF32(acc[mt][nt][0], acc[mt][nt][1], acc[mt][nt][2], acc[mt][nt][3],
                         af[mt][0], af[mt][1], af[mt][2], af[mt][3], b0, b1);
        }
    }
    float* ob = g_t1p + (size_t)n * 64 * H1_P + (2 * u + PY + 1) * 132 + PX + 1;
#pragma unroll
    for (int mt = 0; mt < 4; mt++)
#pragma unroll
        for (int nt = 0; nt < 4; nt++) {
            int co0 = cob + nt * 8 + 2 * lc;
            float* o = ob + 2 * (mt * 16 + lr);
            o[(size_t)co0 * H1_P]            = fmaxf(acc[mt][nt][0], 0.f);
            o[(size_t)(co0 + 1) * H1_P]      = fmaxf(acc[mt][nt][1], 0.f);
            o[(size_t)co0 * H1_P + 16]       = fmaxf(acc[mt][nt][2], 0.f);
            o[(size_t)(co0 + 1) * H1_P + 16] = fmaxf(acc[mt][nt][3], 0.f);
        }
}

__global__ __launch_bounds__(256) void k_dect1(const float* __restrict__ w,
                                               const float* __restrict__ bias) {
    switch (blockIdx.y) {
        case 0: dect1_mma<0, 0>(w, bias); break;
        case 1: dect1_mma<0, 1>(w, bias); break;
        case 2: dect1_mma<1, 0>(w, bias); break;
        default: dect1_mma<1, 1>(w, bias); break;
    }
}

// =====================================================================
// dect2 (tf32 mma v2): per parity M=128x128px, K=256, N=32.
// Warp: M=64 x N=32. CTA: 4u x 2 v-halves.
// grid (1024, 4): x = n*32 + up
// =====================================================================
template<int PY, int PX>
__device__ __forceinline__ void dect2_mma(const float* __restrict__ wgt,
                                          const float* __restrict__ bias) {
    __shared__ unsigned sB[32 * 260];
    int n = blockIdx.x >> 5, up = blockIdx.x & 31;
    int w = threadIdx.x >> 5, lane = threadIdx.x & 31;
    int lr = lane >> 2, lc = lane & 3;
    int u = 4 * up + (w >> 1), v0m = (w & 1) * 64;

    for (int i = threadIdx.x; i < 8192; i += 256) {
        int col = i & 31, k = i >> 5;
        int ci = k >> 2, dy = (k >> 1) & 1, dx = k & 1;
        sB[col * 260 + k] = __float_as_uint(
            wgt[(col * 64 + ci) * 16 + (PY + 2 * dy) * 4 + PX + 2 * dx]);
    }
    __syncthreads();

    float acc[4][4][4];
#pragma unroll
    for (int mt = 0; mt < 4; mt++)
#pragma unroll
        for (int nt = 0; nt < 4; nt++) {
            float b0 = bias[nt * 8 + 2 * lc];
            float b1 = bias[nt * 8 + 2 * lc + 1];
            acc[mt][nt][0] = b0; acc[mt][nt][1] = b1;
            acc[mt][nt][2] = b0; acc[mt][nt][3] = b1;
        }

    int dy = lc >> 1, dx = lc & 1;
    const float* A0 = g_t1p + (size_t)n * 64 * H1_P + (u + PY + dy) * 132
                    + (v0m + PX + dx) + lr;
#pragma unroll 1
    for (int ks = 0; ks < 32; ks++) {
        const float* p0 = A0 + (size_t)(2 * ks) * H1_P;
        unsigned af[4][4];
#pragma unroll
        for (int mt = 0; mt < 4; mt++) {
            const float* pa = p0 + mt * 16;
            af[mt][0] = __float_as_uint(pa[0]);
            af[mt][1] = __float_as_uint(pa[8]);
            af[mt][2] = __float_as_uint(pa[H1_P]);
            af[mt][3] = __float_as_uint(pa[H1_P + 8]);
        }
#pragma unroll
        for (int nt = 0; nt < 4; nt++) {
            unsigned b0 = sB[(nt * 8 + lr) * 260 + 8 * ks + lc];
            unsigned b1 = sB[(nt * 8 + lr) * 260 + 8 * ks + lc + 4];
#pragma unroll
            for (int mt = 0; mt < 4; mt++)
                MMA_TF32(acc[mt][nt][0], acc[mt][nt][1], acc[mt][nt][2], acc[mt][nt][3],
                         af[mt][0], af[mt][1], af[mt][2], af[mt][3], b0, b1);
        }
    }
    float* ob = g_t2p + (size_t)n * 32 * XP_P + (2 * u + PY + 1) * 260
              + PX + 1 + 2 * v0m;
#pragma unroll
    for (int mt = 0; mt < 4; mt++)
#pragma unroll
        for (int nt = 0; nt < 4; nt++) {
            int co0 = nt * 8 + 2 * lc;
            float* o = ob + 2 * (mt * 16 + lr);
            o[(size_t)co0 * XP_P]            = fmaxf(acc[mt][nt][0], 0.f);
            o[(size_t)(co0 + 1) * XP_P]      = fmaxf(acc[mt][nt][1], 0.f);
            o[(size_t)co0 * XP_P + 16]       = fmaxf(acc[mt][nt][2], 0.f);
            o[(size_t)(co0 + 1) * XP_P + 16] = fmaxf(acc[mt][nt][3], 0.f);
        }
}

__global__ __launch_bounds__(256) void k_dect2(const float* __restrict__ w,
                                               const float* __restrict__ bias) {
    switch (blockIdx.y) {
        case 0: dect2_mma<0, 0>(w, bias); break;
        case 1: dect2_mma<0, 1>(w, bias); break;
        case 2: dect2_mma<1, 0>(w, bias); break;
        default: dect2_mma<1, 1>(w, bias); break;
    }
}

// =====================================================================
// dconv2: 3x3 p1, 32->3, sigmoid. 4 px/thread. grid 2048 x 256
// =====================================================================
__global__ __launch_bounds__(256) void k_dconv2(const float* __restrict__ w,
                                                const float* __restrict__ bias,
                                                float* __restrict__ out) {
    __shared__ u64 ws2[32 * 9 * 3];
    for (int i = threadIdx.x; i < 32 * 9; i += 256) {
        int ci = i / 9, k = i % 9;
#pragma unroll
        for (int co = 0; co < 3; co++) {
            float wv = w[(co * 32 + ci) * 9 + k];
            ws2[i * 3 + co] = pack2(wv, wv);
        }
    }
    __syncthreads();
    int n = blockIdx.x >> 6;
    int p = ((blockIdx.x & 63) << 8) + threadIdx.x;
    int X = p & 63, oy = p >> 6;
    int ox0 = 4 * X;

    u64 acc[3][2];
#pragma unroll
    for (int co = 0; co < 3; co++) {
        float bv = bias[co];
        acc[co][0] = pack2(bv, bv);
        acc[co][1] = acc[co][0];
    }
    const float* xin = g_t2p + (size_t)n * 32 * XP_P + oy * 260 + ox0;
    float4 cA[3]; float2 cB[3];
#pragma unroll
    for (int ry = 0; ry < 3; ry++) {
        cA[ry] = *(const float4*)(xin + ry * 260);
        cB[ry] = *(const float2*)(xin + ry * 260 + 4);
    }
#pragma unroll 1
    for (int ci = 0; ci < 32; ci++) {
        const float* pn = xin + (ci < 31 ? ci + 1 : ci) * XP_P;
        float4 nA[3]; float2 nB[3];
#pragma unroll
        for (int ry = 0; ry < 3; ry++) {
            nA[ry] = *(const float4*)(pn + ry * 260);
            nB[ry] = *(const float2*)(pn + ry * 260 + 4);
        }
        float in[3][6];
#pragma unroll
        for (int ry = 0; ry < 3; ry++) {
            *(float4*)&in[ry][0] = cA[ry];
            *(float2*)&in[ry][4] = cB[ry];
        }
        u64 pr[3][5];
#pragma unroll
        for (int ry = 0; ry < 3; ry++)
#pragma unroll
            for (int i = 0; i < 5; i++)
                pr[ry][i] = pack2(in[ry][i], in[ry][i + 1]);
#pragma unroll
        for (int ky = 0; ky < 3; ky++)
#pragma unroll
            for (int kx = 0; kx < 3; kx++) {
                const u64* wr = &ws2[(ci * 9 + ky * 3 + kx) * 3];
#pragma unroll
                for (int co = 0; co < 3; co++) {
                    FFMA2(acc[co][0], pr[ky][kx],     wr[co]);
                    FFMA2(acc[co][1], pr[ky][kx + 2], wr[co]);
                }
            }
#pragma unroll
        for (int ry = 0; ry < 3; ry++) { cA[ry] = nA[ry]; cB[ry] = nB[ry]; }
    }
    float* o = out + (size_t)n * 3 * 65536 + oy * 256 + ox0;
#pragma unroll
    for (int co = 0; co < 3; co++) {
        float2 f0 = unpack2(acc[co][0]);
        float2 f1 = unpack2(acc[co][1]);
        o[co * 65536 + 0] = 1.f / (1.f + expf(-f0.x));
        o[co * 65536 + 1] = 1.f / (1.f + expf(-f0.y));
        o[co * 65536 + 2] = 1.f / (1.f + expf(-f1.x));
        o[co * 65536 + 3] = 1.f / (1.f + expf(-f1.y));
    }
}

// =====================================================================
extern "C" void kernel_launch(void* const* d_in, const int* in_sizes, int n_in,
                              void* d_out, int out_size) {
    const float* x       = (const float*)d_in[0];
    const float* enc_w1  = (const float*)d_in[1];
    const float* enc_b1  = (const float*)d_in[2];
    const float* enc_w2  = (const float*)d_in[3];
    const float* enc_b2  = (const float*)d_in[4];
    const float* enc_w3  = (const float*)d_in[5];
    const float* enc_b3  = (const float*)d_in[6];
    const float* codebook= (const float*)d_in[7];
    const float* dec_w1  = (const float*)d_in[8];
    const float* dec_b1  = (const float*)d_in[9];
    const float* dect_w1 = (const float*)d_in[10];
    const float* dect_b1 = (const float*)d_in[11];
    const float* dect_w2 = (const float*)d_in[12];
    const float* dect_b2 = (const float*)d_in[13];
    const float* dec_w2  = (const float*)d_in[14];
    const float* dec_b2  = (const float*)d_in[15];
    float* out = (float*)d_out;

    k_pad   <<<24576, 256>>>(x);
    k_conv1 <<<1024,  256>>>(enc_w1, enc_b1);
    k_conv2 <<<512,   256>>>(enc_w2, enc_b2);
    k_conv3 <<<512,   256>>>(enc_w3, enc_b3);
    k_vq    <<<1024,  128>>>(codebook);
    k_zq    <<<4096,  256>>>(codebook);
    k_loss  <<<1,     256>>>(out);
    k_idxout<<<512,   256>>>(out);
    k_dconv1<<<512,   256>>>(dec_w1, dec_b1);
    k_dect1 <<<dim3(512, 4),  256>>>(dect_w1, dect_b1);
    k_dect2 <<<dim3(1024, 4), 256>>>(dect_w2, dect_b2);
    k_dconv2<<<2048,  256>>>(dec_w2, dec_b2, out);
}

// round 11
// speedup vs baseline: 1.6660x; 1.1766x over previous
#include <cuda_runtime.h>
#include <math.h>

constexpr int B = 32;

typedef unsigned long long u64;
#define FFMA2(acc, v, w) \
    asm("fma.rn.f32x2 %0, %1, %2, %3;" : "=l"(acc) : "l"(v), "l"(w), "l"(acc))
__device__ __forceinline__ u64 pack2(float a, float b) {
    u64 r; asm("mov.b64 %0, {%1, %2};" : "=l"(r) : "f"(a), "f"(b)); return r;
}
__device__ __forceinline__ float2 unpack2(u64 v) {
    float2 f; asm("mov.b64 {%0, %1}, %2;" : "=f"(f.x), "=f"(f.y) : "l"(v)); return f;
}

#define MMA_TF32(c0, c1, c2, c3, a0, a1, a2, a3, b0, b1) \
    asm("mma.sync.aligned.m16n8k8.row.col.f32.tf32.tf32.f32 " \
        "{%0,%1,%2,%3}, {%4,%5,%6,%7}, {%8,%9}, {%0,%1,%2,%3};" \
        : "+f"(c0), "+f"(c1), "+f"(c2), "+f"(c3) \
        : "r"(a0), "r"(a1), "r"(a2), "r"(a3), "r"(b0), "r"(b1))

// ---- padded planes ----
constexpr int XP_P = 258 * 260;
constexpr int H1_P = 130 * 132;
constexpr int Z_P  = 66 * 68;

__device__ float g_xp [B * 3 * XP_P];
__device__ float g_h1p[B * 32 * H1_P];
__device__ float g_h2 [B * 64 * 4096];
__device__ float g_z  [B * 8 * 4096];
__device__ float g_zqp[B * 8 * Z_P];
__device__ int   g_idx[B * 4096];
__device__ float g_part[4096];
__device__ float g_d1p[B * 64 * Z_P];
__device__ float g_t1p[B * 64 * H1_P];
__device__ float g_t2p[B * 32 * XP_P];

constexpr int XR_ELEMS = B * 3 * 65536;
constexpr int LOSS_OFF = XR_ELEMS;
constexpr int IDX_OFF  = XR_ELEMS + 1;

struct S18 { float4 a, b, c, d; float2 e; };
__device__ __forceinline__ S18 ld18(const float* r) {
    S18 s;
    s.a = *(const float4*)(r);      s.b = *(const float4*)(r + 4);
    s.c = *(const float4*)(r + 8);  s.d = *(const float4*)(r + 12);
    s.e = *(const float2*)(r + 16);
    return s;
}
__device__ __forceinline__ void unp18(const S18& s, float* f) {
    *(float4*)&f[0] = s.a; *(float4*)&f[4] = s.b;
    *(float4*)&f[8] = s.c; *(float4*)&f[12] = s.d;
    *(float2*)&f[16] = s.e;
}

// =====================================================================
__global__ __launch_bounds__(256) void k_pad(const float* __restrict__ x) {
    int i = blockIdx.x * 256 + threadIdx.x;
    int c = i >> 16, hw = i & 65535;
    int y = hw >> 8, xx = hw & 255;
    g_xp[(size_t)c * XP_P + (y + 1) * 260 + xx + 1] = x[i];
}

// =====================================================================
// conv1 (fp32, ENCODER-EXACT): 3->32, k4 s2 p1. grid 1024 x 256
// =====================================================================
__global__ __launch_bounds__(256) void k_conv1(const float* __restrict__ w,
                                               const float* __restrict__ bias) {
    __shared__ float ws[48 * 32];
    for (int i = threadIdx.x; i < 1536; i += 256) {
        int t = i >> 5, co = i & 31;
        int ci = t >> 4, k = t & 15;
        ws[i] = w[(co * 3 + ci) * 16 + k];
    }
    __syncthreads();
    int n = blockIdx.x >> 5, oyg = blockIdx.x & 31;
    int cog = threadIdx.x >> 6, oyl = (threadIdx.x >> 4) & 3, v0 = threadIdx.x & 15;
    int oy = oyg * 4 + oyl, ox0 = v0 * 8;
    u64 acc[4][8];
#pragma unroll
    for (int cp = 0; cp < 4; cp++) {
        u64 bv = pack2(bias[cog * 8 + 2 * cp], bias[cog * 8 + 2 * cp + 1]);
#pragma unroll
        for (int j = 0; j < 8; j++) acc[cp][j] = bv;
    }
    const float* base = g_xp + (size_t)n * 3 * XP_P + 2 * oy * 260 + 2 * ox0;
    S18 cur = ld18(base);
#pragma unroll 1
    for (int idx = 0; idx < 12; idx++) {
        int nx = idx < 11 ? idx + 1 : 11;
        S18 nxt = ld18(base + (nx >> 2) * XP_P + (nx & 3) * 260);
        float f[18]; unp18(cur, f);
        u64 fb[18];
#pragma unroll
        for (int i = 0; i < 18; i++) fb[i] = pack2(f[i], f[i]);
        int ci = idx >> 2, ky = idx & 3;
#pragma unroll
        for (int kx = 0; kx < 4; kx++) {
            const u64* wr = (const u64*)&ws[(ci * 16 + ky * 4 + kx) * 32 + cog * 8];
            u64 w0 = wr[0], w1 = wr[1], w2 = wr[2], w3 = wr[3];
#pragma unroll
            for (int j = 0; j < 8; j++) {
                u64 vv = fb[2 * j + kx];
                FFMA2(acc[0][j], vv, w0); FFMA2(acc[1][j], vv, w1);
                FFMA2(acc[2][j], vv, w2); FFMA2(acc[3][j], vv, w3);
            }
        }
        cur = nxt;
    }
    float* o = g_h1p + (size_t)n * 32 * H1_P + (oy + 1) * 132 + ox0 + 1;
#pragma unroll
    for (int cp = 0; cp < 4; cp++)
#pragma unroll
        for (int j = 0; j < 8; j++) {
            float2 fo = unpack2(acc[cp][j]);
            o[(cog * 8 + 2 * cp)     * H1_P + j] = fmaxf(fo.x, 0.f);
            o[(cog * 8 + 2 * cp + 1) * H1_P + j] = fmaxf(fo.y, 0.f);
        }
}

// =====================================================================
// conv2 (fp32, ENCODER-EXACT): 32->64, k4 s2 p1. grid 512 x 256
// =====================================================================
__global__ __launch_bounds__(256) void k_conv2(const float* __restrict__ w,
                                               const float* __restrict__ bias) {
    __shared__ float ws[8 * 16 * 64];
    int n = blockIdx.x >> 4, oyg = blockIdx.x & 15;
    int cog = threadIdx.x >> 5, oyl = (threadIdx.x >> 3) & 3, v0 = threadIdx.x & 7;
    int oy = oyg * 4 + oyl, ox0 = v0 * 8;
    u64 acc[4][8];
#pragma unroll
    for (int cp = 0; cp < 4; cp++) {
        u64 bv = pack2(bias[cog * 8 + 2 * cp], bias[cog * 8 + 2 * cp + 1]);
#pragma unroll
        for (int j = 0; j < 8; j++) acc[cp][j] = bv;
    }
    const float* xin = g_h1p + (size_t)n * 32 * H1_P + 2 * oy * 132 + 2 * ox0;
#pragma unroll 1
    for (int cc = 0; cc < 4; cc++) {
        __syncthreads();
        for (int i = threadIdx.x; i < 8192; i += 256) {
            int t = i >> 6, co = i & 63;
            int cl = t >> 4, k = t & 15;
            ws[i] = w[(co * 32 + cc * 8 + cl) * 16 + k];
        }
        __syncthreads();
        const float* base = xin + cc * 8 * H1_P;
        S18 cur = ld18(base);
#pragma unroll 1
        for (int idx = 0; idx < 32; idx++) {
            int nx = idx < 31 ? idx + 1 : 31;
            S18 nxt = ld18(base + (nx >> 2) * H1_P + (nx & 3) * 132);
            float f[18]; unp18(cur, f);
            u64 fb[18];
#pragma unroll
            for (int i = 0; i < 18; i++) fb[i] = pack2(f[i], f[i]);
            int cl = idx >> 2, ky = idx & 3;
#pragma unroll
            for (int kx = 0; kx < 4; kx++) {
                const u64* wr = (const u64*)&ws[(cl * 16 + ky * 4 + kx) * 64 + cog * 8];
                u64 w0 = wr[0], w1 = wr[1], w2 = wr[2], w3 = wr[3];
#pragma unroll
                for (int j = 0; j < 8; j++) {
                    u64 vv = fb[2 * j + kx];
                    FFMA2(acc[0][j], vv, w0); FFMA2(acc[1][j], vv, w1);
                    FFMA2(acc[2][j], vv, w2); FFMA2(acc[3][j], vv, w3);
                }
            }
            cur = nxt;
        }
    }
    float* o = g_h2 + (size_t)n * 64 * 4096 + oy * 64 + ox0;
#pragma unroll
    for (int cp = 0; cp < 4; cp++)
#pragma unroll
        for (int j = 0; j < 8; j++) {
            float2 fo = unpack2(acc[cp][j]);
            o[(cog * 8 + 2 * cp)     * 4096 + j] = fmaxf(fo.x, 0.f);
            o[(cog * 8 + 2 * cp + 1) * 4096 + j] = fmaxf(fo.y, 0.f);
        }
}

// =====================================================================
// conv3 (fp32, ENCODER-EXACT): 1x1, 64->8. grid: 512 x 256
// =====================================================================
__global__ __launch_bounds__(256) void k_conv3(const float* __restrict__ w,
                                               const float* __restrict__ bias) {
    __shared__ float ws[64 * 8];
    for (int i = threadIdx.x; i < 512; i += 256) {
        int ci = i >> 3, co = i & 7;
        ws[i] = w[co * 64 + ci];
    }
    __syncthreads();
    int n = blockIdx.x >> 4;
    int p = ((blockIdx.x & 15) << 8) + threadIdx.x;
    u64 acc[4];
#pragma unroll
    for (int c = 0; c < 4; c++) acc[c] = pack2(bias[2 * c], bias[2 * c + 1]);
    const float* xin = g_h2 + (size_t)n * 64 * 4096;
#pragma unroll 8
    for (int ci = 0; ci < 64; ci++) {
        float v = xin[ci * 4096 + p];
        u64 vv = pack2(v, v);
        const u64* wr = (const u64*)&ws[ci * 8];
#pragma unroll
        for (int c = 0; c < 4; c++) FFMA2(acc[c], vv, wr[c]);
    }
    float* o = g_z + (size_t)n * 8 * 4096;
#pragma unroll
    for (int c = 0; c < 4; c++) {
        float2 f = unpack2(acc[c]);
        o[(2 * c)     * 4096 + p] = f.x;
        o[(2 * c + 1) * 4096 + p] = f.y;
    }
}

// =====================================================================
// VQ argmin (exact). grid: 1024 x 128
// =====================================================================
__global__ __launch_bounds__(128) void k_vq(const float* __restrict__ cb) {
    __shared__ float cs[512 * 8];
    __shared__ float csq[512];
    for (int i = threadIdx.x; i < 4096; i += 128) cs[i] = cb[i];
    __syncthreads();
    for (int k = threadIdx.x; k < 512; k += 128) {
        float s = 0.f;
#pragma unroll
        for (int d = 0; d < 8; d++) { float c = cs[k * 8 + d]; s += c * c; }
        csq[k] = s;
    }
    __syncthreads();
    int p = blockIdx.x * 128 + threadIdx.x;
    int n = p >> 12, hw = p & 4095;
    const float* zp = g_z + (size_t)n * 8 * 4096 + hw;
    float zv[8]; float zsq = 0.f;
#pragma unroll
    for (int d = 0; d < 8; d++) { zv[d] = zp[d * 4096]; zsq += zv[d] * zv[d]; }
    float best = 3.4e38f; int bi = 0;
    for (int k = 0; k < 512; k++) {
        float dot = 0.f;
#pragma unroll
        for (int d = 0; d < 8; d++) dot = fmaf(zv[d], cs[k * 8 + d], dot);
        float dist = zsq + csq[k] - 2.f * dot;
        if (dist < best) { best = dist; bi = k; }
    }
    g_idx[p] = bi;
}

// =====================================================================
// z_q gather + loss partials (exact). grid: 4096 x 256
// =====================================================================
__global__ __launch_bounds__(256) void k_zq(const float* __restrict__ cb) {
    int i = blockIdx.x * 256 + threadIdx.x;
    float q = cb[g_idx[i >> 3] * 8 + (i & 7)];
    int n = i >> 15, c = (i >> 12) & 7, hw = i & 4095;
    int y = hw >> 6, xx = hw & 63;
    g_zqp[(size_t)(n * 8 + c) * Z_P + (y + 1) * 68 + xx + 1] = q;
    float diff = g_z[i] - q;
    float v = diff * diff;
    __shared__ float red[256];
    red[threadIdx.x] = v; __syncthreads();
    for (int s = 128; s > 0; s >>= 1) {
        if (threadIdx.x < s) red[threadIdx.x] += red[threadIdx.x + s];
        __syncthreads();
    }
    if (threadIdx.x == 0) g_part[blockIdx.x] = red[0];
}

__global__ __launch_bounds__(256) void k_loss(float* __restrict__ out) {
    __shared__ float red[256];
    float s = 0.f;
    for (int i = threadIdx.x; i < 4096; i += 256) s += g_part[i];
    red[threadIdx.x] = s; __syncthreads();
    for (int st = 128; st > 0; st >>= 1) {
        if (threadIdx.x < st) red[threadIdx.x] += red[threadIdx.x + st];
        __syncthreads();
    }
    if (threadIdx.x == 0) out[LOSS_OFF] = red[0] * (1.25f / 1048576.f);
}

__global__ __launch_bounds__(256) void k_idxout(float* __restrict__ out) {
    int p = blockIdx.x * 256 + threadIdx.x;
    if (p < B * 4096) out[IDX_OFF + p] = (float)g_idx[p];
}

// =====================================================================
// dconv1 (tf32 mma): 3x3 p1, 8->64. K = 72 tap-major (k = tap*8 + ci).
// Warp: M=64 (one oy row) x N=32. CTA 8 warps: 4 oy x 2 co-halves.
// grid 512 x 256: x = n*16 + oyb
// =====================================================================
__global__ __launch_bounds__(256) void k_dconv1(const float* __restrict__ wgt,
                                                const float* __restrict__ bias) {
    __shared__ unsigned sB[64 * 76];  // [co][k], k stride 76, K=72
    int n = blockIdx.x >> 4, oyb = blockIdx.x & 15;
    int w = threadIdx.x >> 5, lane = threadIdx.x & 31;
    int lr = lane >> 2, lc = lane & 3;
    int oy = oyb * 4 + (w >> 1), cob = (w & 1) * 32;

    for (int i = threadIdx.x; i < 4608; i += 256) {
        int col = i & 63, k = i >> 6;  // k 0..71
        int ci = k & 7, tap = k >> 3;
        sB[col * 76 + k] = __float_as_uint(wgt[(col * 8 + ci) * 9 + tap]);
    }
    __syncthreads();

    float acc[4][4][4];
#pragma unroll
    for (int mt = 0; mt < 4; mt++)
#pragma unroll
        for (int nt = 0; nt < 4; nt++) {
            float b0 = bias[cob + nt * 8 + 2 * lc];
            float b1 = bias[cob + nt * 8 + 2 * lc + 1];
            acc[mt][nt][0] = b0; acc[mt][nt][1] = b1;
            acc[mt][nt][2] = b0; acc[mt][nt][3] = b1;
        }

    // A: in_p[ci][oy+ky][m+kx], ci = lc (+4), m = mt*16+lr (+8)
    const float* A0 = g_zqp + (size_t)n * 8 * Z_P + (size_t)lc * Z_P
                    + oy * 68 + lr;
#pragma unroll 1
    for (int ks = 0; ks < 9; ks++) {
        int ky = ks / 3, kx = ks - 3 * ky;
        const float* p0 = A0 + ky * 68 + kx;
        unsigned af[4][4];
#pragma unroll
        for (int mt = 0; mt < 4; mt++) {
            const float* pa = p0 + mt * 16;
            af[mt][0] = __float_as_uint(pa[0]);
            af[mt][1] = __float_as_uint(pa[8]);
            af[mt][2] = __float_as_uint(pa[4 * Z_P]);
            af[mt][3] = __float_as_uint(pa[4 * Z_P + 8]);
        }
#pragma unroll
        for (int nt = 0; nt < 4; nt++) {
            unsigned b0 = sB[(cob + nt * 8 + lr) * 76 + 8 * ks + lc];
            unsigned b1 = sB[(cob + nt * 8 + lr) * 76 + 8 * ks + lc + 4];
#pragma unroll
            for (int mt = 0; mt < 4; mt++)
                MMA_TF32(acc[mt][nt][0], acc[mt][nt][1], acc[mt][nt][2], acc[mt][nt][3],
                         af[mt][0], af[mt][1], af[mt][2], af[mt][3], b0, b1);
        }
    }
    float* ob = g_d1p + (size_t)n * 64 * Z_P + (oy + 1) * 68 + 1;
#pragma unroll
    for (int mt = 0; mt < 4; mt++)
#pragma unroll
        for (int nt = 0; nt < 4; nt++) {
            int co0 = cob + nt * 8 + 2 * lc;
            float* o = ob + mt * 16 + lr;
            o[(size_t)co0 * Z_P]           = fmaxf(acc[mt][nt][0], 0.f);
            o[(size_t)(co0 + 1) * Z_P]     = fmaxf(acc[mt][nt][1], 0.f);
            o[(size_t)co0 * Z_P + 8]       = fmaxf(acc[mt][nt][2], 0.f);
            o[(size_t)(co0 + 1) * Z_P + 8] = fmaxf(acc[mt][nt][3], 0.f);
        }
}

// =====================================================================
// dect1 (tf32 mma v3): per parity M=64x64px, K=256, N=64 per warp.
// CTA 8 warps = 8 u-rows. K chunked 2x128. grid (256, 4): x = n*8 + ub
// =====================================================================
template<int PY, int PX>
__device__ __forceinline__ void dect1_mma(const float* __restrict__ wgt,
                                          const float* __restrict__ bias) {
    __shared__ unsigned sB[64 * 132];  // [co][kl], kl stride 132 (K-chunk 128)
    int n = blockIdx.x >> 3, ub = blockIdx.x & 7;
    int w = threadIdx.x >> 5, lane = threadIdx.x & 31;
    int lr = lane >> 2, lc = lane & 3;
    int u = 8 * ub + w;

    float acc[4][8][4];
#pragma unroll
    for (int mt = 0; mt < 4; mt++)
#pragma unroll
        for (int nt = 0; nt < 8; nt++) {
            float b0 = bias[nt * 8 + 2 * lc];
            float b1 = bias[nt * 8 + 2 * lc + 1];
            acc[mt][nt][0] = b0; acc[mt][nt][1] = b1;
            acc[mt][nt][2] = b0; acc[mt][nt][3] = b1;
        }

    int dy = lc >> 1, dx = lc & 1;
    const float* A0 = g_d1p + (size_t)n * 64 * Z_P + (u + PY + dy) * 68
                    + (PX + dx) + lr;
#pragma unroll 1
    for (int cc = 0; cc < 2; cc++) {
        __syncthreads();
        for (int i = threadIdx.x; i < 8192; i += 256) {
            int col = i & 63, kl = i >> 6;  // kl 0..127
            int ci = (cc * 128 + kl) >> 2, ddy = (kl >> 1) & 1, ddx = kl & 1;
            sB[col * 132 + kl] = __float_as_uint(
                wgt[(col * 64 + ci) * 16 + (PY + 2 * ddy) * 4 + PX + 2 * ddx]);
        }
        __syncthreads();
#pragma unroll 1
        for (int ksl = 0; ksl < 16; ksl++) {
            const float* p0 = A0 + (size_t)(cc * 32 + 2 * ksl) * Z_P;
            unsigned af[4][4];
#pragma unroll
            for (int mt = 0; mt < 4; mt++) {
                const float* pa = p0 + mt * 16;
                af[mt][0] = __float_as_uint(pa[0]);
                af[mt][1] = __float_as_uint(pa[8]);
                af[mt][2] = __float_as_uint(pa[Z_P]);
                af[mt][3] = __float_as_uint(pa[Z_P + 8]);
            }
#pragma unroll
            for (int nt = 0; nt < 8; nt++) {
                unsigned b0 = sB[(nt * 8 + lr) * 132 + 8 * ksl + lc];
                unsigned b1 = sB[(nt * 8 + lr) * 132 + 8 * ksl + lc + 4];
#pragma unroll
                for (int mt = 0; mt < 4; mt++)
                    MMA_TF32(acc[mt][nt][0], acc[mt][nt][1], acc[mt][nt][2], acc[mt][nt][3],
                             af[mt][0], af[mt][1], af[mt][2], af[mt][3], b0, b1);
            }
        }
    }
    float* ob = g_t1p + (size_t)n * 64 * H1_P + (2 * u + PY + 1) * 132 + PX + 1;
#pragma unroll
    for (int mt = 0; mt < 4; mt++)
#pragma unroll
        for (int nt = 0; nt < 8; nt++) {
            int co0 = nt * 8 + 2 * lc;
            float* o = ob + 2 * (mt * 16 + lr);
            o[(size_t)co0 * H1_P]            = fmaxf(acc[mt][nt][0], 0.f);
            o[(size_t)(co0 + 1) * H1_P]      = fmaxf(acc[mt][nt][1], 0.f);
            o[(size_t)co0 * H1_P + 16]       = fmaxf(acc[mt][nt][2], 0.f);
            o[(size_t)(co0 + 1) * H1_P + 16] = fmaxf(acc[mt][nt][3], 0.f);
        }
}

__global__ __launch_bounds__(256) void k_dect1(const float* __restrict__ w,
                                               const float* __restrict__ bias) {
    switch (blockIdx.y) {
        case 0: dect1_mma<0, 0>(w, bias); break;
        case 1: dect1_mma<0, 1>(w, bias); break;
        case 2: dect1_mma<1, 0>(w, bias); break;
        default: dect1_mma<1, 1>(w, bias); break;
    }
}

// =====================================================================
// dect2 (tf32 mma v3): per parity M=128x128px, K=256, N=32.
// Warp: M=128 (full v row) x N=32. CTA 8 warps = 8 u-rows.
// grid (512, 4): x = n*16 + up
// =====================================================================
template<int PY, int PX>
__device__ __forceinline__ void dect2_mma(const float* __restrict__ wgt,
                                          const float* __restrict__ bias) {
    __shared__ unsigned sB[32 * 260];  // full K=256
    int n = blockIdx.x >> 4, up = blockIdx.x & 15;
    int w = threadIdx.x >> 5, lane = threadIdx.x & 31;
    int lr = lane >> 2, lc = lane & 3;
    int u = 8 * up + w;

    for (int i = threadIdx.x; i < 8192; i += 256) {
        int col = i & 31, k = i >> 5;
        int ci = k >> 2, ddy = (k >> 1) & 1, ddx = k & 1;
        sB[col * 260 + k] = __float_as_uint(
            wgt[(col * 64 + ci) * 16 + (PY + 2 * ddy) * 4 + PX + 2 * ddx]);
    }
    __syncthreads();

    float acc[8][4][4];
#pragma unroll
    for (int mt = 0; mt < 8; mt++)
#pragma unroll
        for (int nt = 0; nt < 4; nt++) {
            float b0 = bias[nt * 8 + 2 * lc];
            float b1 = bias[nt * 8 + 2 * lc + 1];
            acc[mt][nt][0] = b0; acc[mt][nt][1] = b1;
            acc[mt][nt][2] = b0; acc[mt][nt][3] = b1;
        }

    int dy = lc >> 1, dx = lc & 1;
    const float* A0 = g_t1p + (size_t)n * 64 * H1_P + (u + PY + dy) * 132
                    + (PX + dx) + lr;
#pragma unroll 1
    for (int ks = 0; ks < 32; ks++) {
        const float* p0 = A0 + (size_t)(2 * ks) * H1_P;
        unsigned af[8][4];
#pragma unroll
        for (int mt = 0; mt < 8; mt++) {
            const float* pa = p0 + mt * 16;
            af[mt][0] = __float_as_uint(pa[0]);
            af[mt][1] = __float_as_uint(pa[8]);
            af[mt][2] = __float_as_uint(pa[H1_P]);
            af[mt][3] = __float_as_uint(pa[H1_P + 8]);
        }
#pragma unroll
        for (int nt = 0; nt < 4; nt++) {
            unsigned b0 = sB[(nt * 8 + lr) * 260 + 8 * ks + lc];
            unsigned b1 = sB[(nt * 8 + lr) * 260 + 8 * ks + lc + 4];
#pragma unroll
            for (int mt = 0; mt < 8; mt++)
                MMA_TF32(acc[mt][nt][0], acc[mt][nt][1], acc[mt][nt][2], acc[mt][nt][3],
                         af[mt][0], af[mt][1], af[mt][2], af[mt][3], b0, b1);
        }
    }
    float* ob = g_t2p + (size_t)n * 32 * XP_P + (2 * u + PY + 1) * 260 + PX + 1;
#pragma unroll
    for (int mt = 0; mt < 8; mt++)
#pragma unroll
        for (int nt = 0; nt < 4; nt++) {
            int co0 = nt * 8 + 2 * lc;
            float* o = ob + 2 * (mt * 16 + lr);
            o[(size_t)co0 * XP_P]            = fmaxf(acc[mt][nt][0], 0.f);
            o[(size_t)(co0 + 1) * XP_P]      = fmaxf(acc[mt][nt][1], 0.f);
            o[(size_t)co0 * XP_P + 16]       = fmaxf(acc[mt][nt][2], 0.f);
            o[(size_t)(co0 + 1) * XP_P + 16] = fmaxf(acc[mt][nt][3], 0.f);
        }
}

__global__ __launch_bounds__(256) void k_dect2(const float* __restrict__ w,
                                               const float* __restrict__ bias) {
    switch (blockIdx.y) {
        case 0: dect2_mma<0, 0>(w, bias); break;
        case 1: dect2_mma<0, 1>(w, bias); break;
        case 2: dect2_mma<1, 0>(w, bias); break;
        default: dect2_mma<1, 1>(w, bias); break;
    }
}

// =====================================================================
// dconv2 (fp32): 3x3 p1, 32->3, sigmoid. 4 px/thread. grid 2048 x 256
// =====================================================================
__global__ __launch_bounds__(256) void k_dconv2(const float* __restrict__ w,
                                                const float* __restrict__ bias,
                                                float* __restrict__ out) {
    __shared__ u64 ws2[32 * 9 * 3];
    for (int i = threadIdx.x; i < 32 * 9; i += 256) {
        int ci = i / 9, k = i % 9;
#pragma unroll
        for (int co = 0; co < 3; co++) {
            float wv = w[(co * 32 + ci) * 9 + k];
            ws2[i * 3 + co] = pack2(wv, wv);
        }
    }
    __syncthreads();
    int n = blockIdx.x >> 6;
    int p = ((blockIdx.x & 63) << 8) + threadIdx.x;
    int X = p & 63, oy = p >> 6;
    int ox0 = 4 * X;

    u64 acc[3][2];
#pragma unroll
    for (int co = 0; co < 3; co++) {
        float bv = bias[co];
        acc[co][0] = pack2(bv, bv);
        acc[co][1] = acc[co][0];
    }
    const float* xin = g_t2p + (size_t)n * 32 * XP_P + oy * 260 + ox0;
    float4 cA[3]; float2 cB[3];
#pragma unroll
    for (int ry = 0; ry < 3; ry++) {
        cA[ry] = *(const float4*)(xin + ry * 260);
        cB[ry] = *(const float2*)(xin + ry * 260 + 4);
    }
#pragma unroll 1
    for (int ci = 0; ci < 32; ci++) {
        const float* pn = xin + (ci < 31 ? ci + 1 : ci) * XP_P;
        float4 nA[3]; float2 nB[3];
#pragma unroll
        for (int ry = 0; ry < 3; ry++) {
            nA[ry] = *(const float4*)(pn + ry * 260);
            nB[ry] = *(const float2*)(pn + ry * 260 + 4);
        }
        float in[3][6];
#pragma unroll
        for (int ry = 0; ry < 3; ry++) {
            *(float4*)&in[ry][0] = cA[ry];
            *(float2*)&in[ry][4] = cB[ry];
        }
        u64 pr[3][5];
#pragma unroll
        for (int ry = 0; ry < 3; ry++)
#pragma unroll
            for (int i = 0; i < 5; i++)
                pr[ry][i] = pack2(in[ry][i], in[ry][i + 1]);
#pragma unroll
        for (int ky = 0; ky < 3; ky++)
#pragma unroll
            for (int kx = 0; kx < 3; kx++) {
                const u64* wr = &ws2[(ci * 9 + ky * 3 + kx) * 3];
#pragma unroll
                for (int co = 0; co < 3; co++) {
                    FFMA2(acc[co][0], pr[ky][kx],     wr[co]);
                    FFMA2(acc[co][1], pr[ky][kx + 2], wr[co]);
                }
            }
#pragma unroll
        for (int ry = 0; ry < 3; ry++) { cA[ry] = nA[ry]; cB[ry] = nB[ry]; }
    }
    float* o = out + (size_t)n * 3 * 65536 + oy * 256 + ox0;
#pragma unroll
    for (int co = 0; co < 3; co++) {
        float2 f0 = unpack2(acc[co][0]);
        float2 f1 = unpack2(acc[co][1]);
        o[co * 65536 + 0] = 1.f / (1.f + expf(-f0.x));
        o[co * 65536 + 1] = 1.f / (1.f + expf(-f0.y));
        o[co * 65536 + 2] = 1.f / (1.f + expf(-f1.x));
        o[co * 65536 + 3] = 1.f / (1.f + expf(-f1.y));
    }
}

// =====================================================================
extern "C" void kernel_launch(void* const* d_in, const int* in_sizes, int n_in,
                              void* d_out, int out_size) {
    const float* x       = (const float*)d_in[0];
    const float* enc_w1  = (const float*)d_in[1];
    const float* enc_b1  = (const float*)d_in[2];
    const float* enc_w2  = (const float*)d_in[3];
    const float* enc_b2  = (const float*)d_in[4];
    const float* enc_w3  = (const float*)d_in[5];
    const float* enc_b3  = (const float*)d_in[6];
    const float* codebook= (const float*)d_in[7];
    const float* dec_w1  = (const float*)d_in[8];
    const float* dec_b1  = (const float*)d_in[9];
    const float* dect_w1 = (const float*)d_in[10];
    const float* dect_b1 = (const float*)d_in[11];
    const float* dect_w2 = (const float*)d_in[12];
    const float* dect_b2 = (const float*)d_in[13];
    const float* dec_w2  = (const float*)d_in[14];
    const float* dec_b2  = (const float*)d_in[15];
    float* out = (float*)d_out;

    k_pad   <<<24576, 256>>>(x);
    k_conv1 <<<1024,  256>>>(enc_w1, enc_b1);
    k_conv2 <<<512,   256>>>(enc_w2, enc_b2);
    k_conv3 <<<512,   256>>>(enc_w3, enc_b3);
    k_vq    <<<1024,  128>>>(codebook);
    k_zq    <<<4096,  256>>>(codebook);
    k_loss  <<<1,     256>>>(out);
    k_idxout<<<512,   256>>>(out);
    k_dconv1<<<512,   256>>>(dec_w1, dec_b1);
    k_dect1 <<<dim3(256, 4),  256>>>(dect_w1, dect_b1);
    k_dect2 <<<dim3(512, 4),  256>>>(dect_w2, dect_b2);
    k_dconv2<<<2048,  256>>>(dec_w2, dec_b2, out);
}

// round 12
// speedup vs baseline: 1.8551x; 1.1136x over previous
#include <cuda_runtime.h>
#include <math.h>

constexpr int B = 32;

typedef unsigned long long u64;
#define FFMA2(acc, v, w) \
    asm("fma.rn.f32x2 %0, %1, %2, %3;" : "=l"(acc) : "l"(v), "l"(w), "l"(acc))
__device__ __forceinline__ u64 pack2(float a, float b) {
    u64 r; asm("mov.b64 %0, {%1, %2};" : "=l"(r) : "f"(a), "f"(b)); return r;
}
__device__ __forceinline__ float2 unpack2(u64 v) {
    float2 f; asm("mov.b64 {%0, %1}, %2;" : "=f"(f.x), "=f"(f.y) : "l"(v)); return f;
}

#define MMA_TF32(c0, c1, c2, c3, a0, a1, a2, a3, b0, b1) \
    asm("mma.sync.aligned.m16n8k8.row.col.f32.tf32.tf32.f32 " \
        "{%0,%1,%2,%3}, {%4,%5,%6,%7}, {%8,%9}, {%0,%1,%2,%3};" \
        : "+f"(c0), "+f"(c1), "+f"(c2), "+f"(c3) \
        : "r"(a0), "r"(a1), "r"(a2), "r"(a3), "r"(b0), "r"(b1))

// ---- padded planes ----
constexpr int XP_P = 258 * 260;
constexpr int H1_P = 130 * 132;
constexpr int Z_P  = 66 * 68;

__device__ float g_xp [B * 3 * XP_P];
__device__ float g_h1p[B * 32 * H1_P];
__device__ float g_h2 [B * 64 * 4096];
__device__ float g_z  [B * 8 * 4096];
__device__ float g_zqp[B * 8 * Z_P];
__device__ int   g_idx[B * 4096];
__device__ float g_part[4096];
__device__ float g_d1p[B * 64 * Z_P];
__device__ float g_t1p[B * 64 * H1_P];
__device__ float g_t2p[B * 32 * XP_P];

constexpr int XR_ELEMS = B * 3 * 65536;
constexpr int LOSS_OFF = XR_ELEMS;
constexpr int IDX_OFF  = XR_ELEMS + 1;

struct S18 { float4 a, b, c, d; float2 e; };
__device__ __forceinline__ S18 ld18(const float* r) {
    S18 s;
    s.a = *(const float4*)(r);      s.b = *(const float4*)(r + 4);
    s.c = *(const float4*)(r + 8);  s.d = *(const float4*)(r + 12);
    s.e = *(const float2*)(r + 16);
    return s;
}
__device__ __forceinline__ void unp18(const S18& s, float* f) {
    *(float4*)&f[0] = s.a; *(float4*)&f[4] = s.b;
    *(float4*)&f[8] = s.c; *(float4*)&f[12] = s.d;
    *(float2*)&f[16] = s.e;
}

// =====================================================================
__global__ __launch_bounds__(256) void k_pad(const float* __restrict__ x) {
    int i = blockIdx.x * 256 + threadIdx.x;
    int c = i >> 16, hw = i & 65535;
    int y = hw >> 8, xx = hw & 255;
    g_xp[(size_t)c * XP_P + (y + 1) * 260 + xx + 1] = x[i];
}

// =====================================================================
// conv1 (fp32, ENCODER-EXACT): 3->32, k4 s2 p1. grid 1024 x 256
// =====================================================================
__global__ __launch_bounds__(256) void k_conv1(const float* __restrict__ w,
                                               const float* __restrict__ bias) {
    __shared__ float ws[48 * 32];
    for (int i = threadIdx.x; i < 1536; i += 256) {
        int t = i >> 5, co = i & 31;
        int ci = t >> 4, k = t & 15;
        ws[i] = w[(co * 3 + ci) * 16 + k];
    }
    __syncthreads();
    int n = blockIdx.x >> 5, oyg = blockIdx.x & 31;
    int cog = threadIdx.x >> 6, oyl = (threadIdx.x >> 4) & 3, v0 = threadIdx.x & 15;
    int oy = oyg * 4 + oyl, ox0 = v0 * 8;
    u64 acc[4][8];
#pragma unroll
    for (int cp = 0; cp < 4; cp++) {
        u64 bv = pack2(bias[cog * 8 + 2 * cp], bias[cog * 8 + 2 * cp + 1]);
#pragma unroll
        for (int j = 0; j < 8; j++) acc[cp][j] = bv;
    }
    const float* base = g_xp + (size_t)n * 3 * XP_P + 2 * oy * 260 + 2 * ox0;
    S18 cur = ld18(base);
#pragma unroll 1
    for (int idx = 0; idx < 12; idx++) {
        int nx = idx < 11 ? idx + 1 : 11;
        S18 nxt = ld18(base + (nx >> 2) * XP_P + (nx & 3) * 260);
        float f[18]; unp18(cur, f);
        u64 fb[18];
#pragma unroll
        for (int i = 0; i < 18; i++) fb[i] = pack2(f[i], f[i]);
        int ci = idx >> 2, ky = idx & 3;
#pragma unroll
        for (int kx = 0; kx < 4; kx++) {
            const u64* wr = (const u64*)&ws[(ci * 16 + ky * 4 + kx) * 32 + cog * 8];
            u64 w0 = wr[0], w1 = wr[1], w2 = wr[2], w3 = wr[3];
#pragma unroll
            for (int j = 0; j < 8; j++) {
                u64 vv = fb[2 * j + kx];
                FFMA2(acc[0][j], vv, w0); FFMA2(acc[1][j], vv, w1);
                FFMA2(acc[2][j], vv, w2); FFMA2(acc[3][j], vv, w3);
            }
        }
        cur = nxt;
    }
    float* o = g_h1p + (size_t)n * 32 * H1_P + (oy + 1) * 132 + ox0 + 1;
#pragma unroll
    for (int cp = 0; cp < 4; cp++)
#pragma unroll
        for (int j = 0; j < 8; j++) {
            float2 fo = unpack2(acc[cp][j]);
            o[(cog * 8 + 2 * cp)     * H1_P + j] = fmaxf(fo.x, 0.f);
            o[(cog * 8 + 2 * cp + 1) * H1_P + j] = fmaxf(fo.y, 0.f);
        }
}

// =====================================================================
// conv2 (fp32, ENCODER-EXACT): 32->64, k4 s2 p1. grid 512 x 256
// =====================================================================
__global__ __launch_bounds__(256) void k_conv2(const float* __restrict__ w,
                                               const float* __restrict__ bias) {
    __shared__ float ws[8 * 16 * 64];
    int n = blockIdx.x >> 4, oyg = blockIdx.x & 15;
    int cog = threadIdx.x >> 5, oyl = (threadIdx.x >> 3) & 3, v0 = threadIdx.x & 7;
    int oy = oyg * 4 + oyl, ox0 = v0 * 8;
    u64 acc[4][8];
#pragma unroll
    for (int cp = 0; cp < 4; cp++) {
        u64 bv = pack2(bias[cog * 8 + 2 * cp], bias[cog * 8 + 2 * cp + 1]);
#pragma unroll
        for (int j = 0; j < 8; j++) acc[cp][j] = bv;
    }
    const float* xin = g_h1p + (size_t)n * 32 * H1_P + 2 * oy * 132 + 2 * ox0;
#pragma unroll 1
    for (int cc = 0; cc < 4; cc++) {
        __syncthreads();
        for (int i = threadIdx.x; i < 8192; i += 256) {
            int t = i >> 6, co = i & 63;
            int cl = t >> 4, k = t & 15;
            ws[i] = w[(co * 32 + cc * 8 + cl) * 16 + k];
        }
        __syncthreads();
        const float* base = xin + cc * 8 * H1_P;
        S18 cur = ld18(base);
#pragma unroll 1
        for (int idx = 0; idx < 32; idx++) {
            int nx = idx < 31 ? idx + 1 : 31;
            S18 nxt = ld18(base + (nx >> 2) * H1_P + (nx & 3) * 132);
            float f[18]; unp18(cur, f);
            u64 fb[18];
#pragma unroll
            for (int i = 0; i < 18; i++) fb[i] = pack2(f[i], f[i]);
            int cl = idx >> 2, ky = idx & 3;
#pragma unroll
            for (int kx = 0; kx < 4; kx++) {
                const u64* wr = (const u64*)&ws[(cl * 16 + ky * 4 + kx) * 64 + cog * 8];
                u64 w0 = wr[0], w1 = wr[1], w2 = wr[2], w3 = wr[3];
#pragma unroll
                for (int j = 0; j < 8; j++) {
                    u64 vv = fb[2 * j + kx];
                    FFMA2(acc[0][j], vv, w0); FFMA2(acc[1][j], vv, w1);
                    FFMA2(acc[2][j], vv, w2); FFMA2(acc[3][j], vv, w3);
                }
            }
            cur = nxt;
        }
    }
    float* o = g_h2 + (size_t)n * 64 * 4096 + oy * 64 + ox0;
#pragma unroll
    for (int cp = 0; cp < 4; cp++)
#pragma unroll
        for (int j = 0; j < 8; j++) {
            float2 fo = unpack2(acc[cp][j]);
            o[(cog * 8 + 2 * cp)     * 4096 + j] = fmaxf(fo.x, 0.f);
            o[(cog * 8 + 2 * cp + 1) * 4096 + j] = fmaxf(fo.y, 0.f);
        }
}

// =====================================================================
// conv3 (fp32, ENCODER-EXACT): 1x1, 64->8. grid: 512 x 256
// =====================================================================
__global__ __launch_bounds__(256) void k_conv3(const float* __restrict__ w,
                                               const float* __restrict__ bias) {
    __shared__ float ws[64 * 8];
    for (int i = threadIdx.x; i < 512; i += 256) {
        int ci = i >> 3, co = i & 7;
        ws[i] = w[co * 64 + ci];
    }
    __syncthreads();
    int n = blockIdx.x >> 4;
    int p = ((blockIdx.x & 15) << 8) + threadIdx.x;
    u64 acc[4];
#pragma unroll
    for (int c = 0; c < 4; c++) acc[c] = pack2(bias[2 * c], bias[2 * c + 1]);
    const float* xin = g_h2 + (size_t)n * 64 * 4096;
#pragma unroll 8
    for (int ci = 0; ci < 64; ci++) {
        float v = xin[ci * 4096 + p];
        u64 vv = pack2(v, v);
        const u64* wr = (const u64*)&ws[ci * 8];
#pragma unroll
        for (int c = 0; c < 4; c++) FFMA2(acc[c], vv, wr[c]);
    }
    float* o = g_z + (size_t)n * 8 * 4096;
#pragma unroll
    for (int c = 0; c < 4; c++) {
        float2 f = unpack2(acc[c]);
        o[(2 * c)     * 4096 + p] = f.x;
        o[(2 * c + 1) * 4096 + p] = f.y;
    }
}

// =====================================================================
// VQ argmin (exact). grid: 1024 x 128
// =====================================================================
__global__ __launch_bounds__(128) void k_vq(const float* __restrict__ cb) {
    __shared__ float cs[512 * 8];
    __shared__ float csq[512];
    for (int i = threadIdx.x; i < 4096; i += 128) cs[i] = cb[i];
    __syncthreads();
    for (int k = threadIdx.x; k < 512; k += 128) {
        float s = 0.f;
#pragma unroll
        for (int d = 0; d < 8; d++) { float c = cs[k * 8 + d]; s += c * c; }
        csq[k] = s;
    }
    __syncthreads();
    int p = blockIdx.x * 128 + threadIdx.x;
    int n = p >> 12, hw = p & 4095;
    const float* zp = g_z + (size_t)n * 8 * 4096 + hw;
    float zv[8]; float zsq = 0.f;
#pragma unroll
    for (int d = 0; d < 8; d++) { zv[d] = zp[d * 4096]; zsq += zv[d] * zv[d]; }
    float best = 3.4e38f; int bi = 0;
    for (int k = 0; k < 512; k++) {
        float dot = 0.f;
#pragma unroll
        for (int d = 0; d < 8; d++) dot = fmaf(zv[d], cs[k * 8 + d], dot);
        float dist = zsq + csq[k] - 2.f * dot;
        if (dist < best) { best = dist; bi = k; }
    }
    g_idx[p] = bi;
}

// =====================================================================
// z_q gather + loss partials + idx output (exact). grid: 4096 x 256
// =====================================================================
__global__ __launch_bounds__(256) void k_zq(const float* __restrict__ cb,
                                            float* __restrict__ out) {
    int i = blockIdx.x * 256 + threadIdx.x;
    int ii = i >> 3;
    int idxv = g_idx[ii];
    float q = cb[idxv * 8 + (i & 7)];
    int n = i >> 15, c = (i >> 12) & 7, hw = i & 4095;
    int y = hw >> 6, xx = hw & 63;
    g_zqp[(size_t)(n * 8 + c) * Z_P + (y + 1) * 68 + xx + 1] = q;
    if ((i & 7) == 0) out[IDX_OFF + ii] = (float)idxv;
    float diff = g_z[i] - q;
    float v = diff * diff;
    __shared__ float red[256];
    red[threadIdx.x] = v; __syncthreads();
    for (int s = 128; s > 0; s >>= 1) {
        if (threadIdx.x < s) red[threadIdx.x] += red[threadIdx.x + s];
        __syncthreads();
    }
    if (threadIdx.x == 0) g_part[blockIdx.x] = red[0];
}

__global__ __launch_bounds__(256) void k_loss(float* __restrict__ out) {
    __shared__ float red[256];
    float s = 0.f;
    for (int i = threadIdx.x; i < 4096; i += 256) s += g_part[i];
    red[threadIdx.x] = s; __syncthreads();
    for (int st = 128; st > 0; st >>= 1) {
        if (threadIdx.x < st) red[threadIdx.x] += red[threadIdx.x + st];
        __syncthreads();
    }
    if (threadIdx.x == 0) out[LOSS_OFF] = red[0] * (1.25f / 1048576.f);
}

// =====================================================================
// dconv1 (tf32 mma): 3x3 p1, 8->64. K = 72 tap-major. grid 512 x 256
// =====================================================================
__global__ __launch_bounds__(256) void k_dconv1(const float* __restrict__ wgt,
                                                const float* __restrict__ bias) {
    __shared__ unsigned sB[64 * 76];
    int n = blockIdx.x >> 4, oyb = blockIdx.x & 15;
    int w = threadIdx.x >> 5, lane = threadIdx.x & 31;
    int lr = lane >> 2, lc = lane & 3;
    int oy = oyb * 4 + (w >> 1), cob = (w & 1) * 32;

    for (int i = threadIdx.x; i < 4608; i += 256) {
        int col = i & 63, k = i >> 6;
        int ci = k & 7, tap = k >> 3;
        sB[col * 76 + k] = __float_as_uint(wgt[(col * 8 + ci) * 9 + tap]);
    }
    __syncthreads();

    float acc[4][4][4];
#pragma unroll
    for (int mt = 0; mt < 4; mt++)
#pragma unroll
        for (int nt = 0; nt < 4; nt++) {
            float b0 = bias[cob + nt * 8 + 2 * lc];
            float b1 = bias[cob + nt * 8 + 2 * lc + 1];
            acc[mt][nt][0] = b0; acc[mt][nt][1] = b1;
            acc[mt][nt][2] = b0; acc[mt][nt][3] = b1;
        }

    const float* A0 = g_zqp + (size_t)n * 8 * Z_P + (size_t)lc * Z_P
                    + oy * 68 + lr;
#pragma unroll 1
    for (int ks = 0; ks < 9; ks++) {
        int ky = ks / 3, kx = ks - 3 * ky;
        const float* p0 = A0 + ky * 68 + kx;
        unsigned af[4][4];
#pragma unroll
        for (int mt = 0; mt < 4; mt++) {
            const float* pa = p0 + mt * 16;
            af[mt][0] = __float_as_uint(pa[0]);
            af[mt][1] = __float_as_uint(pa[8]);
            af[mt][2] = __float_as_uint(pa[4 * Z_P]);
            af[mt][3] = __float_as_uint(pa[4 * Z_P + 8]);
        }
#pragma unroll
        for (int nt = 0; nt < 4; nt++) {
            unsigned b0 = sB[(cob + nt * 8 + lr) * 76 + 8 * ks + lc];
            unsigned b1 = sB[(cob + nt * 8 + lr) * 76 + 8 * ks + lc + 4];
#pragma unroll
            for (int mt = 0; mt < 4; mt++)
                MMA_TF32(acc[mt][nt][0], acc[mt][nt][1], acc[mt][nt][2], acc[mt][nt][3],
                         af[mt][0], af[mt][1], af[mt][2], af[mt][3], b0, b1);
        }
    }
    float* ob = g_d1p + (size_t)n * 64 * Z_P + (oy + 1) * 68 + 1;
#pragma unroll
    for (int mt = 0; mt < 4; mt++)
#pragma unroll
        for (int nt = 0; nt < 4; nt++) {
            int co0 = cob + nt * 8 + 2 * lc;
            float* o = ob + mt * 16 + lr;
            o[(size_t)co0 * Z_P]           = fmaxf(acc[mt][nt][0], 0.f);
            o[(size_t)(co0 + 1) * Z_P]     = fmaxf(acc[mt][nt][1], 0.f);
            o[(size_t)co0 * Z_P + 8]       = fmaxf(acc[mt][nt][2], 0.f);
            o[(size_t)(co0 + 1) * Z_P + 8] = fmaxf(acc[mt][nt][3], 0.f);
        }
}

// =====================================================================
// dect1 (tf32 mma v4, pipelined): per parity M=64, K=256, N=64/warp.
// CTA 8 warps = 8 u. K chunked 2x128. grid (256, 4)
// =====================================================================
template<int PY, int PX>
__device__ __forceinline__ void dect1_mma(const float* __restrict__ wgt,
                                          const float* __restrict__ bias) {
    __shared__ unsigned sB[64 * 132];
    int n = blockIdx.x >> 3, ub = blockIdx.x & 7;
    int w = threadIdx.x >> 5, lane = threadIdx.x & 31;
    int lr = lane >> 2, lc = lane & 3;
    int u = 8 * ub + w;

    float acc[4][8][4];
#pragma unroll
    for (int mt = 0; mt < 4; mt++)
#pragma unroll
        for (int nt = 0; nt < 8; nt++) {
            float b0 = bias[nt * 8 + 2 * lc];
            float b1 = bias[nt * 8 + 2 * lc + 1];
            acc[mt][nt][0] = b0; acc[mt][nt][1] = b1;
            acc[mt][nt][2] = b0; acc[mt][nt][3] = b1;
        }

    int dy = lc >> 1, dx = lc & 1;
    const float* A0 = g_d1p + (size_t)n * 64 * Z_P + (u + PY + dy) * 68
                    + (PX + dx) + lr;
#pragma unroll 1
    for (int cc = 0; cc < 2; cc++) {
        __syncthreads();
        for (int i = threadIdx.x; i < 8192; i += 256) {
            int col = i & 63, kl = i >> 6;
            int ci = (cc * 128 + kl) >> 2, ddy = (kl >> 1) & 1, ddx = kl & 1;
            sB[col * 132 + kl] = __float_as_uint(
                wgt[(col * 64 + ci) * 16 + (PY + 2 * ddy) * 4 + PX + 2 * ddx]);
        }
        __syncthreads();
        const float* Ac = A0 + (size_t)(cc * 32) * Z_P;
        unsigned af0[4][4], af1[4][4];
#pragma unroll
        for (int mt = 0; mt < 4; mt++) {
            const float* pa = Ac + mt * 16;
            af0[mt][0] = __float_as_uint(pa[0]);
            af0[mt][1] = __float_as_uint(pa[8]);
            af0[mt][2] = __float_as_uint(pa[Z_P]);
            af0[mt][3] = __float_as_uint(pa[Z_P + 8]);
        }
#pragma unroll 1
        for (int ksl = 0; ksl < 16; ksl += 2) {
            // prefetch ksl+1
            {
                const float* p1 = Ac + (size_t)(2 * (ksl + 1)) * Z_P;
#pragma unroll
                for (int mt = 0; mt < 4; mt++) {
                    const float* pa = p1 + mt * 16;
                    af1[mt][0] = __float_as_uint(pa[0]);
                    af1[mt][1] = __float_as_uint(pa[8]);
                    af1[mt][2] = __float_as_uint(pa[Z_P]);
                    af1[mt][3] = __float_as_uint(pa[Z_P + 8]);
                }
            }
#pragma unroll
            for (int nt = 0; nt < 8; nt++) {
                unsigned b0 = sB[(nt * 8 + lr) * 132 + 8 * ksl + lc];
                unsigned b1 = sB[(nt * 8 + lr) * 132 + 8 * ksl + lc + 4];
#pragma unroll
                for (int mt = 0; mt < 4; mt++)
                    MMA_TF32(acc[mt][nt][0], acc[mt][nt][1], acc[mt][nt][2], acc[mt][nt][3],
                             af0[mt][0], af0[mt][1], af0[mt][2], af0[mt][3], b0, b1);
            }
            // prefetch ksl+2 (clamped)
            {
                int k2 = ksl + 2 < 16 ? ksl + 2 : 15;
                const float* p2 = Ac + (size_t)(2 * k2) * Z_P;
#pragma unroll
                for (int mt = 0; mt < 4; mt++) {
                    const float* pa = p2 + mt * 16;
                    af0[mt][0] = __float_as_uint(pa[0]);
                    af0[mt][1] = __float_as_uint(pa[8]);
                    af0[mt][2] = __float_as_uint(pa[Z_P]);
                    af0[mt][3] = __float_as_uint(pa[Z_P + 8]);
                }
            }
#pragma unroll
            for (int nt = 0; nt < 8; nt++) {
                unsigned b0 = sB[(nt * 8 + lr) * 132 + 8 * (ksl + 1) + lc];
                unsigned b1 = sB[(nt * 8 + lr) * 132 + 8 * (ksl + 1) + lc + 4];
#pragma unroll
                for (int mt = 0; mt < 4; mt++)
                    MMA_TF32(acc[mt][nt][0], acc[mt][nt][1], acc[mt][nt][2], acc[mt][nt][3],
                             af1[mt][0], af1[mt][1], af1[mt][2], af1[mt][3], b0, b1);
            }
        }
    }
    float* ob = g_t1p + (size_t)n * 64 * H1_P + (2 * u + PY + 1) * 132 + PX + 1;
#pragma unroll
    for (int mt = 0; mt < 4; mt++)
#pragma unroll
        for (int nt = 0; nt < 8; nt++) {
            int co0 = nt * 8 + 2 * lc;
            float* o = ob + 2 * (mt * 16 + lr);
            o[(size_t)co0 * H1_P]            = fmaxf(acc[mt][nt][0], 0.f);
            o[(size_t)(co0 + 1) * H1_P]      = fmaxf(acc[mt][nt][1], 0.f);
            o[(size_t)co0 * H1_P + 16]       = fmaxf(acc[mt][nt][2], 0.f);
            o[(size_t)(co0 + 1) * H1_P + 16] = fmaxf(acc[mt][nt][3], 0.f);
        }
}

__global__ __launch_bounds__(256) void k_dect1(const float* __restrict__ w,
                                               const float* __restrict__ bias) {
    switch (blockIdx.y) {
        case 0: dect1_mma<0, 0>(w, bias); break;
        case 1: dect1_mma<0, 1>(w, bias); break;
        case 2: dect1_mma<1, 0>(w, bias); break;
        default: dect1_mma<1, 1>(w, bias); break;
    }
}

// =====================================================================
// dect2 (tf32 mma v4, pipelined): per parity M=128/warp, K=256, N=32.
// CTA 8 warps = 8 u. grid (512, 4)
// =====================================================================
template<int PY, int PX>
__device__ __forceinline__ void dect2_mma(const float* __restrict__ wgt,
                                          const float* __restrict__ bias) {
    __shared__ unsigned sB[32 * 260];
    int n = blockIdx.x >> 4, up = blockIdx.x & 15;
    int w = threadIdx.x >> 5, lane = threadIdx.x & 31;
    int lr = lane >> 2, lc = lane & 3;
    int u = 8 * up + w;

    for (int i = threadIdx.x; i < 8192; i += 256) {
        int col = i & 31, k = i >> 5;
        int ci = k >> 2, ddy = (k >> 1) & 1, ddx = k & 1;
        sB[col * 260 + k] = __float_as_uint(
            wgt[(col * 64 + ci) * 16 + (PY + 2 * ddy) * 4 + PX + 2 * ddx]);
    }
    __syncthreads();

    float acc[8][4][4];
#pragma unroll
    for (int mt = 0; mt < 8; mt++)
#pragma unroll
        for (int nt = 0; nt < 4; nt++) {
            float b0 = bias[nt * 8 + 2 * lc];
            float b1 = bias[nt * 8 + 2 * lc + 1];
            acc[mt][nt][0] = b0; acc[mt][nt][1] = b1;
            acc[mt][nt][2] = b0; acc[mt][nt][3] = b1;
        }

    int dy = lc >> 1, dx = lc & 1;
    const float* A0 = g_t1p + (size_t)n * 64 * H1_P + (u + PY + dy) * 132
                    + (PX + dx) + lr;
    unsigned af0[8][4], af1[8][4];
#pragma unroll
    for (int mt = 0; mt < 8; mt++) {
        const float* pa = A0 + mt * 16;
        af0[mt][0] = __float_as_uint(pa[0]);
        af0[mt][1] = __float_as_uint(pa[8]);
        af0[mt][2] = __float_as_uint(pa[H1_P]);
        af0[mt][3] = __float_as_uint(pa[H1_P + 8]);
    }
#pragma unroll 1
    for (int ks = 0; ks < 32; ks += 2) {
        {
            const float* p1 = A0 + (size_t)(2 * (ks + 1)) * H1_P;
#pragma unroll
            for (int mt = 0; mt < 8; mt++) {
                const float* pa = p1 + mt * 16;
                af1[mt][0] = __float_as_uint(pa[0]);
                af1[mt][1] = __float_as_uint(pa[8]);
                af1[mt][2] = __float_as_uint(pa[H1_P]);
                af1[mt][3] = __float_as_uint(pa[H1_P + 8]);
            }
        }
#pragma unroll
        for (int nt = 0; nt < 4; nt++) {
            unsigned b0 = sB[(nt * 8 + lr) * 260 + 8 * ks + lc];
            unsigned b1 = sB[(nt * 8 + lr) * 260 + 8 * ks + lc + 4];
#pragma unroll
            for (int mt = 0; mt < 8; mt++)
                MMA_TF32(acc[mt][nt][0], acc[mt][nt][1], acc[mt][nt][2], acc[mt][nt][3],
                         af0[mt][0], af0[mt][1], af0[mt][2], af0[mt][3], b0, b1);
        }
        {
            int k2 = ks + 2 < 32 ? ks + 2 : 31;
            const float* p2 = A0 + (size_t)(2 * k2) * H1_P;
#pragma unroll
            for (int mt = 0; mt < 8; mt++) {
                const float* pa = p2 + mt * 16;
                af0[mt][0] = __float_as_uint(pa[0]);
                af0[mt][1] = __float_as_uint(pa[8]);
                af0[mt][2] = __float_as_uint(pa[H1_P]);
                af0[mt][3] = __float_as_uint(pa[H1_P + 8]);
            }
        }
#pragma unroll
        for (int nt = 0; nt < 4; nt++) {
            unsigned b0 = sB[(nt * 8 + lr) * 260 + 8 * (ks + 1) + lc];
            unsigned b1 = sB[(nt * 8 + lr) * 260 + 8 * (ks + 1) + lc + 4];
#pragma unroll
            for (int mt = 0; mt < 8; mt++)
                MMA_TF32(acc[mt][nt][0], acc[mt][nt][1], acc[mt][nt][2], acc[mt][nt][3],
                         af1[mt][0], af1[mt][1], af1[mt][2], af1[mt][3], b0, b1);
        }
    }
    float* ob = g_t2p + (size_t)n * 32 * XP_P + (2 * u + PY + 1) * 260 + PX + 1;
#pragma unroll
    for (int mt = 0; mt < 8; mt++)
#pragma unroll
        for (int nt = 0; nt < 4; nt++) {
            int co0 = nt * 8 + 2 * lc;
            float* o = ob + 2 * (mt * 16 + lr);
            o[(size_t)co0 * XP_P]            = fmaxf(acc[mt][nt][0], 0.f);
            o[(size_t)(co0 + 1) * XP_P]      = fmaxf(acc[mt][nt][1], 0.f);
            o[(size_t)co0 * XP_P + 16]       = fmaxf(acc[mt][nt][2], 0.f);
            o[(size_t)(co0 + 1) * XP_P + 16] = fmaxf(acc[mt][nt][3], 0.f);
        }
}

__global__ __launch_bounds__(256) void k_dect2(const float* __restrict__ w,
                                               const float* __restrict__ bias) {
    switch (blockIdx.y) {
        case 0: dect2_mma<0, 0>(w, bias); break;
        case 1: dect2_mma<0, 1>(w, bias); break;
        case 2: dect2_mma<1, 0>(w, bias); break;
        default: dect2_mma<1, 1>(w, bias); break;
    }
}

// =====================================================================
// dconv2 (fp32): 3x3 p1, 32->3, sigmoid. 4 px/thread. grid 2048 x 256
// =====================================================================
__global__ __launch_bounds__(256) void k_dconv2(const float* __restrict__ w,
                                                const float* __restrict__ bias,
                                                float* __restrict__ out) {
    __shared__ u64 ws2[32 * 9 * 3];
    for (int i = threadIdx.x; i < 32 * 9; i += 256) {
        int ci = i / 9, k = i % 9;
#pragma unroll
        for (int co = 0; co < 3; co++) {
            float wv = w[(co * 32 + ci) * 9 + k];
            ws2[i * 3 + co] = pack2(wv, wv);
        }
    }
    __syncthreads();
    int n = blockIdx.x >> 6;
    int p = ((blockIdx.x & 63) << 8) + threadIdx.x;
    int X = p & 63, oy = p >> 6;
    int ox0 = 4 * X;

    u64 acc[3][2];
#pragma unroll
    for (int co = 0; co < 3; co++) {
        float bv = bias[co];
        acc[co][0] = pack2(bv, bv);
        acc[co][1] = acc[co][0];
    }
    const float* xin = g_t2p + (size_t)n * 32 * XP_P + oy * 260 + ox0;
    float4 cA[3]; float2 cB[3];
#pragma unroll
    for (int ry = 0; ry < 3; ry++) {
        cA[ry] = *(const float4*)(xin + ry * 260);
        cB[ry] = *(const float2*)(xin + ry * 260 + 4);
    }
#pragma unroll 1
    for (int ci = 0; ci < 32; ci++) {
        const float* pn = xin + (ci < 31 ? ci + 1 : ci) * XP_P;
        float4 nA[3]; float2 nB[3];
#pragma unroll
        for (int ry = 0; ry < 3; ry++) {
            nA[ry] = *(const float4*)(pn + ry * 260);
            nB[ry] = *(const float2*)(pn + ry * 260 + 4);
        }
        float in[3][6];
#pragma unroll
        for (int ry = 0; ry < 3; ry++) {
            *(float4*)&in[ry][0] = cA[ry];
            *(float2*)&in[ry][4] = cB[ry];
        }
        u64 pr[3][5];
#pragma unroll
        for (int ry = 0; ry < 3; ry++)
#pragma unroll
            for (int i = 0; i < 5; i++)
                pr[ry][i] = pack2(in[ry][i], in[ry][i + 1]);
#pragma unroll
        for (int ky = 0; ky < 3; ky++)
#pragma unroll
            for (int kx = 0; kx < 3; kx++) {
                const u64* wr = &ws2[(ci * 9 + ky * 3 + kx) * 3];
#pragma unroll
                for (int co = 0; co < 3; co++) {
                    FFMA2(acc[co][0], pr[ky][kx],     wr[co]);
                    FFMA2(acc[co][1], pr[ky][kx + 2], wr[co]);
                }
            }
#pragma unroll
        for (int ry = 0; ry < 3; ry++) { cA[ry] = nA[ry]; cB[ry] = nB[ry]; }
    }
    float* o = out + (size_t)n * 3 * 65536 + oy * 256 + ox0;
#pragma unroll
    for (int co = 0; co < 3; co++) {
        float2 f0 = unpack2(acc[co][0]);
        float2 f1 = unpack2(acc[co][1]);
        o[co * 65536 + 0] = 1.f / (1.f + expf(-f0.x));
        o[co * 65536 + 1] = 1.f / (1.f + expf(-f0.y));
        o[co * 65536 + 2] = 1.f / (1.f + expf(-f1.x));
        o[co * 65536 + 3] = 1.f / (1.f + expf(-f1.y));
    }
}

// =====================================================================
extern "C" void kernel_launch(void* const* d_in, const int* in_sizes, int n_in,
                              void* d_out, int out_size) {
    const float* x       = (const float*)d_in[0];
    const float* enc_w1  = (const float*)d_in[1];
    const float* enc_b1  = (const float*)d_in[2];
    const float* enc_w2  = (const float*)d_in[3];
    const float* enc_b2  = (const float*)d_in[4];
    const float* enc_w3  = (const float*)d_in[5];
    const float* enc_b3  = (const float*)d_in[6];
    const float* codebook= (const float*)d_in[7];
    const float* dec_w1  = (const float*)d_in[8];
    const float* dec_b1  = (const float*)d_in[9];
    const float* dect_w1 = (const float*)d_in[10];
    const float* dect_b1 = (const float*)d_in[11];
    const float* dect_w2 = (const float*)d_in[12];
    const float* dect_b2 = (const float*)d_in[13];
    const float* dec_w2  = (const float*)d_in[14];
    const float* dec_b2  = (const float*)d_in[15];
    float* out = (float*)d_out;

    k_pad   <<<24576, 256>>>(x);
    k_conv1 <<<1024,  256>>>(enc_w1, enc_b1);
    k_conv2 <<<512,   256>>>(enc_w2, enc_b2);
    k_conv3 <<<512,   256>>>(enc_w3, enc_b3);
    k_vq    <<<1024,  128>>>(codebook);
    k_zq    <<<4096,  256>>>(codebook, out);
    k_loss  <<<1,     256>>>(out);
    k_dconv1<<<512,   256>>>(dec_w1, dec_b1);
    k_dect1 <<<dim3(256, 4),  256>>>(dect_w1, dect_b1);
    k_dect2 <<<dim3(512, 4),  256>>>(dect_w2, dect_b2);
    k_dconv2<<<2048,  256>>>(dec_w2, dec_b2, out);
}